// round 7
// baseline (speedup 1.0000x reference)
#include <cuda_runtime.h>

#define WARPS 15
#define THREADS (WARPS * 32)
#define MAXN 20
#define CH 10

// ---- prep scratch layout (floats) ----
// staged block (copied to smem by each block):
//   [0,8448)      mp1_w1 padded [64][132]
//   [8448,16896)  mp2_w1 padded [64][132]
//   [16896,21248) mp1_w2 padded [64][68]
//   [21248,25600) mp2_w2 padded [64][68]
#define STAGED_FLOATS 25600
__device__ __align__(16) float g_staged[STAGED_FLOATS];
__device__ float2 g_wihT2[72 * 96];   // [k][gate][lane] -> {W[g*64+l][k], W[g*64+l+32][k]}
__device__ float2 g_whhT2[64 * 96];
__device__ float2 g_pqT2[64 * 32];
__device__ float  g_headsT[64 * 32];  // [k][t], t: 0-7 op, 8-17 c1, 18-27 c2, 28-31 zero

__global__ void prep_kernel(const float* __restrict__ mp1_w1, const float* __restrict__ mp1_w2,
                            const float* __restrict__ mp2_w1, const float* __restrict__ mp2_w2,
                            const float* __restrict__ gru_wih, const float* __restrict__ gru_whh,
                            const float* __restrict__ pq_w,
                            const float* __restrict__ op_w, const float* __restrict__ c1_w,
                            const float* __restrict__ c2_w)
{
    const int tid = blockIdx.x * blockDim.x + threadIdx.x;
    const int stride = gridDim.x * blockDim.x;
    for (int i = tid; i < 64 * 132; i += stride) {
        int r = i / 132, c = i % 132;
        g_staged[i]        = (c < 128) ? mp1_w1[r * 128 + c] : 0.f;
        g_staged[8448 + i] = (c < 128) ? mp2_w1[r * 128 + c] : 0.f;
    }
    for (int i = tid; i < 64 * 68; i += stride) {
        int r = i / 68, c = i % 68;
        g_staged[16896 + i] = (c < 64) ? mp1_w2[r * 64 + c] : 0.f;
        g_staged[21248 + i] = (c < 64) ? mp2_w2[r * 64 + c] : 0.f;
    }
    for (int i = tid; i < 72 * 96; i += stride) {
        int k = i / 96, g = (i % 96) / 32, l = i % 32;
        g_wihT2[i] = make_float2(gru_wih[(g * 64 + l) * 72 + k],
                                 gru_wih[(g * 64 + l + 32) * 72 + k]);
    }
    for (int i = tid; i < 64 * 96; i += stride) {
        int k = i / 96, g = (i % 96) / 32, l = i % 32;
        g_whhT2[i] = make_float2(gru_whh[(g * 64 + l) * 64 + k],
                                 gru_whh[(g * 64 + l + 32) * 64 + k]);
    }
    for (int i = tid; i < 64 * 32; i += stride) {
        int k = i / 32, l = i % 32;
        g_pqT2[i] = make_float2(pq_w[l * 64 + k], pq_w[(l + 32) * 64 + k]);
        float hv = 0.f;
        if (l < 8)       hv = op_w[l * 64 + k];
        else if (l < 18) hv = c1_w[(l - 8) * 64 + k];
        else if (l < 28) hv = c2_w[(l - 18) * 64 + k];
        g_headsT[i] = hv;
    }
}

__device__ __forceinline__ void fma4(float& acc, const float4 a, const float4 b) {
    acc = fmaf(a.x, b.x, acc);
    acc = fmaf(a.y, b.y, acc);
    acc = fmaf(a.z, b.z, acc);
    acc = fmaf(a.w, b.w, acc);
}

__device__ __forceinline__ float wsum(float v) {
#pragma unroll
    for (int o = 16; o > 0; o >>= 1) v += __shfl_xor_sync(0xffffffffu, v, o);
    return v;
}

// per-warp activation floats: sh(1280) su(640) sm(64) sa(64) sb(64) = 2112
#define ACT_FLOATS 2112
#define SMEM_FLOATS (STAGED_FLOATS + WARPS * ACT_FLOATS)

__global__ void __launch_bounds__(THREADS)
mp_kernel(const float* __restrict__ node_feats, const int* __restrict__ n_nodes,
          const float* __restrict__ rnn_state, const float* __restrict__ prev_op,
          const float* __restrict__ ne_w, const float* __restrict__ ne_b,
          const float* __restrict__ mp1_b1, const float* __restrict__ mp1_b2,
          const float* __restrict__ n1_g, const float* __restrict__ n1_b,
          const float* __restrict__ mp2_b1, const float* __restrict__ mp2_b2,
          const float* __restrict__ n2_g, const float* __restrict__ n2_b,
          const float* __restrict__ gru_bih, const float* __restrict__ gru_bhh,
          const float* __restrict__ op_b, const float* __restrict__ c1_b,
          const float* __restrict__ c2_b,
          const float* __restrict__ pq_b,
          const float* __restrict__ pk_w, const float* __restrict__ pk_b,
          float* __restrict__ out, int B)
{
    extern __shared__ float smem[];

    // ---- stage weights (all threads) ----
    {
        const float4* src = (const float4*)g_staged;
        float4* dst = (float4*)smem;
        for (int i = threadIdx.x; i < STAGED_FLOATS / 4; i += THREADS) dst[i] = src[i];
    }
    __syncthreads();

    const int warp = threadIdx.x >> 5;
    const int lane = threadIdx.x & 31;
    const long b = (long)blockIdx.x * WARPS + warp;
    if (b >= B) return;

    const int o0 = lane, o1 = lane + 32;
    const int cnt = n_nodes[b];
    const float inv = 1.0f / (float)cnt;

    float* W1s0 = smem;
    float* W1s1 = smem + 8448;
    float* W2s0 = smem + 16896;
    float* W2s1 = smem + 21248;
    float* sh = smem + STAGED_FLOATS + warp * ACT_FLOATS;
    float* su = sh + 1280;
    float* sm = su + 640;
    float* sa = sm + 64;
    float* sb = sa + 64;

    const long OC1 = (long)B * 8;
    const long OC2 = (long)B * 18;
    const long OPTR = (long)B * 28;
    const long OST = (long)B * 48;

    // ---- load node feats (only cnt rows needed) into su (alias) ----
    {
        const float4* nf = (const float4*)(node_feats + b * (MAXN * 16));
        float4* d4 = (float4*)su;
        const int tot4 = cnt * 4;
        for (int i = lane; i < tot4; i += 32) d4[i] = nf[i];
    }
    const float st0 = rnn_state[b * 64 + o0];
    const float st1 = rnn_state[b * 64 + o1];
    sa[o0] = st0; sa[o1] = st1;
    const float4 pva = *(const float4*)(prev_op + b * 8);
    const float4 pvb = *(const float4*)(prev_op + b * 8 + 4);
    __syncwarp();

    // ---- encoder: h = nf @ ne_w^T + ne_b ; msg = masked mean ----
    float msg0 = 0.f, msg1 = 0.f;
    {
        float4 w0[4], w1[4];
#pragma unroll
        for (int kc = 0; kc < 4; kc++) {
            w0[kc] = *(const float4*)(ne_w + o0 * 16 + kc * 4);
            w1[kc] = *(const float4*)(ne_w + o1 * 16 + kc * 4);
        }
        const float nb0 = ne_b[o0], nb1 = ne_b[o1];
#pragma unroll
        for (int c = 0; c < 2; c++) {
            const int base = c * CH;
            if (base < cnt) {
                float a0[CH], a1[CH];
#pragma unroll
                for (int i = 0; i < CH; i++) { a0[i] = nb0; a1[i] = nb1; }
#pragma unroll
                for (int kc = 0; kc < 4; kc++) {
#pragma unroll
                    for (int i = 0; i < CH; i++) {
                        float4 xv = *(const float4*)(su + (base + i) * 16 + kc * 4);
                        fma4(a0[i], xv, w0[kc]);
                        fma4(a1[i], xv, w1[kc]);
                    }
                }
#pragma unroll
                for (int i = 0; i < CH; i++) {
                    const int n = base + i;
                    if (n < cnt) {
                        msg0 += a0[i]; msg1 += a1[i];
                        sh[n * 64 + o0] = a0[i];
                        sh[n * 64 + o1] = a1[i];
                    }
                }
            }
        }
    }
    msg0 *= inv; msg1 *= inv;
    __syncwarp();
    sm[o0] = msg0; sm[o1] = msg1;
    __syncwarp();

    // ---- two message-passing blocks (weights in smem, padded strides) ----
#pragma unroll 1
    for (int blk = 0; blk < 2; blk++) {
        const float* w1r0 = (blk ? W1s1 : W1s0) + o0 * 132;
        const float* w1r1 = (blk ? W1s1 : W1s0) + o1 * 132;
        const float* w2r0 = (blk ? W2s1 : W2s0) + o0 * 68;
        const float* w2r1 = (blk ? W2s1 : W2s0) + o1 * 68;
        const float* b1p = blk ? mp2_b1 : mp1_b1;
        const float* b2p = blk ? mp2_b2 : mp1_b2;
        const float* gp  = blk ? n2_g : n1_g;
        const float* lbp = blk ? n2_b : n1_b;

        // msg-dependent part of layer1 (row-invariant)
        float mm0 = b1p[o0], mm1 = b1p[o1];
#pragma unroll
        for (int kc = 0; kc < 16; kc++) {
            float4 xv = *(const float4*)(sm + kc * 4);
            fma4(mm0, xv, *(const float4*)(w1r0 + 64 + kc * 4));
            fma4(mm1, xv, *(const float4*)(w1r1 + 64 + kc * 4));
        }
        const float bb20 = b2p[o0], bb21 = b2p[o1];
        const float g0 = gp[o0], g1 = gp[o1];
        const float lb0 = lbp[o0], lb1 = lbp[o1];

        float nm0 = 0.f, nm1 = 0.f;
#pragma unroll
        for (int c = 0; c < 2; c++) {
            const int base = c * CH;
            if (base < cnt) {
                // layer1: u = relu(h @ W1a^T + mm)
                float a0[CH], a1[CH];
#pragma unroll
                for (int i = 0; i < CH; i++) { a0[i] = mm0; a1[i] = mm1; }
#pragma unroll
                for (int kc = 0; kc < 16; kc++) {
                    float4 wa = *(const float4*)(w1r0 + kc * 4);
                    float4 wb = *(const float4*)(w1r1 + kc * 4);
#pragma unroll
                    for (int i = 0; i < CH; i++) {
                        float4 xv = *(const float4*)(sh + (base + i) * 64 + kc * 4);
                        fma4(a0[i], xv, wa);
                        fma4(a1[i], xv, wb);
                    }
                }
#pragma unroll
                for (int i = 0; i < CH; i++) {
                    su[i * 64 + o0] = fmaxf(a0[i], 0.f);
                    su[i * 64 + o1] = fmaxf(a1[i], 0.f);
                }
                __syncwarp();
                // layer2 + residual + LN + mask
                float v0[CH], v1[CH];
#pragma unroll
                for (int i = 0; i < CH; i++) { v0[i] = bb20; v1[i] = bb21; }
#pragma unroll
                for (int kc = 0; kc < 16; kc++) {
                    float4 wa = *(const float4*)(w2r0 + kc * 4);
                    float4 wb = *(const float4*)(w2r1 + kc * 4);
#pragma unroll
                    for (int i = 0; i < CH; i++) {
                        float4 xv = *(const float4*)(su + i * 64 + kc * 4);
                        fma4(v0[i], xv, wa);
                        fma4(v1[i], xv, wb);
                    }
                }
#pragma unroll
                for (int i = 0; i < CH; i++) {
                    const int n = base + i;
                    if (n < cnt) {
                        float x0 = v0[i] + sh[n * 64 + o0];
                        float x1v = v1[i] + sh[n * 64 + o1];
                        float mu = wsum(x0 + x1v) * (1.0f / 64.0f);
                        float d0 = x0 - mu, d1 = x1v - mu;
                        float var = wsum(d0 * d0 + d1 * d1) * (1.0f / 64.0f);
                        float rs = rsqrtf(var + 1e-5f);
                        float h0 = d0 * rs * g0 + lb0;
                        float h1 = d1 * rs * g1 + lb1;
                        nm0 += h0; nm1 += h1;
                        sh[n * 64 + o0] = h0;
                        sh[n * 64 + o1] = h1;
                    }
                }
                __syncwarp();
            }
        }
        msg0 = nm0 * inv; msg1 = nm1 * inv;
        __syncwarp();
        sm[o0] = msg0; sm[o1] = msg1;
        __syncwarp();
    }

    // ---- GRU cell via transposed, lane-pair-packed weights (coalesced) ----
    float gir0 = gru_bih[o0],       gir1 = gru_bih[o1];
    float giz0 = gru_bih[64 + o0],  giz1 = gru_bih[64 + o1];
    float gin0 = gru_bih[128 + o0], gin1 = gru_bih[128 + o1];
    float ghr0 = gru_bhh[o0],       ghr1 = gru_bhh[o1];
    float ghz0 = gru_bhh[64 + o0],  ghz1 = gru_bhh[64 + o1];
    float ghn0 = gru_bhh[128 + o0], ghn1 = gru_bhh[128 + o1];
#pragma unroll 4
    for (int k = 0; k < 64; k++) {
        const float xm = sm[k];
        const float2* wk = g_wihT2 + k * 96;
        const float2 wr = wk[lane];
        const float2 wz = wk[32 + lane];
        const float2 wn = wk[64 + lane];
        gir0 = fmaf(xm, wr.x, gir0); gir1 = fmaf(xm, wr.y, gir1);
        giz0 = fmaf(xm, wz.x, giz0); giz1 = fmaf(xm, wz.y, giz1);
        gin0 = fmaf(xm, wn.x, gin0); gin1 = fmaf(xm, wn.y, gin1);
        const float xs = sa[k];
        const float2* vk = g_whhT2 + k * 96;
        const float2 vr = vk[lane];
        const float2 vz = vk[32 + lane];
        const float2 vn = vk[64 + lane];
        ghr0 = fmaf(xs, vr.x, ghr0); ghr1 = fmaf(xs, vr.y, ghr1);
        ghz0 = fmaf(xs, vz.x, ghz0); ghz1 = fmaf(xs, vz.y, ghz1);
        ghn0 = fmaf(xs, vn.x, ghn0); ghn1 = fmaf(xs, vn.y, ghn1);
    }
    {
        const float pv[8] = {pva.x, pva.y, pva.z, pva.w, pvb.x, pvb.y, pvb.z, pvb.w};
#pragma unroll
        for (int k = 0; k < 8; k++) {
            const float xp = pv[k];
            const float2* wk = g_wihT2 + (64 + k) * 96;
            const float2 wr = wk[lane];
            const float2 wz = wk[32 + lane];
            const float2 wn = wk[64 + lane];
            gir0 = fmaf(xp, wr.x, gir0); gir1 = fmaf(xp, wr.y, gir1);
            giz0 = fmaf(xp, wz.x, giz0); giz1 = fmaf(xp, wz.y, giz1);
            gin0 = fmaf(xp, wn.x, gin0); gin1 = fmaf(xp, wn.y, gin1);
        }
    }

    const float r0 = 1.0f / (1.0f + expf(-(gir0 + ghr0)));
    const float r1 = 1.0f / (1.0f + expf(-(gir1 + ghr1)));
    const float z0 = 1.0f / (1.0f + expf(-(giz0 + ghz0)));
    const float z1 = 1.0f / (1.0f + expf(-(giz1 + ghz1)));
    const float nn0 = tanhf(gin0 + r0 * ghn0);
    const float nn1 = tanhf(gin1 + r1 * ghn1);
    const float ns0 = (1.0f - z0) * nn0 + z0 * st0;
    const float ns1 = (1.0f - z1) * nn1 + z1 * st1;

    out[OST + b * 64 + o0] = ns0;
    out[OST + b * 64 + o1] = ns1;
    sb[o0] = ns0; sb[o1] = ns1;
    __syncwarp();

    // ---- heads via transposed matrix (coalesced; one output per lane) ----
    {
        float hb = 0.f; long off = -1;
        if (lane < 8)       { hb = op_b[lane];      off = b * 8 + lane; }
        else if (lane < 18) { hb = c1_b[lane - 8];  off = OC1 + b * 10 + (lane - 8); }
        else if (lane < 28) { hb = c2_b[lane - 18]; off = OC2 + b * 10 + (lane - 18); }
        float acc = hb;
#pragma unroll 4
        for (int k = 0; k < 64; k++) acc = fmaf(sb[k], g_headsT[k * 32 + lane], acc);
        if (off >= 0) out[off] = acc;
    }

    // ---- query via transposed pq, then qa = pk_w^T @ q ----
    float q0 = pq_b[o0], q1 = pq_b[o1];
#pragma unroll 4
    for (int k = 0; k < 64; k++) {
        const float xv = sb[k];
        const float2 w = g_pqT2[k * 32 + lane];
        q0 = fmaf(xv, w.x, q0); q1 = fmaf(xv, w.y, q1);
    }
    __syncwarp();
    sa[o0] = q0; sa[o1] = q1;
    __syncwarp();

    float qa0 = 0.f, qa1 = 0.f;
#pragma unroll 8
    for (int o = 0; o < 64; o++) {
        const float qv = sa[o];
        qa0 = fmaf(qv, pk_w[o * 64 + o0], qa0);
        qa1 = fmaf(qv, pk_w[o * 64 + o1], qa1);
    }
    const float qb = wsum(q0 * pk_b[o0] + q1 * pk_b[o1]);

    // ---- pointer logits ----
    for (int n = 0; n < cnt; n++) {
        float p = sh[n * 64 + o0] * qa0 + sh[n * 64 + o1] * qa1;
        float val = wsum(p) + qb;
        if (lane == 0) out[OPTR + b * 20 + n] = val;
    }
    for (int n = cnt + lane; n < MAXN; n += 32) out[OPTR + b * 20 + n] = -1e9f;
}

extern "C" void kernel_launch(void* const* d_in, const int* in_sizes, int n_in,
                              void* d_out, int out_size) {
    const int B = in_sizes[1];  // n_nodes element count

    prep_kernel<<<64, 256>>>(
        (const float*)d_in[6],  (const float*)d_in[8],   // mp1_w1, mp1_w2
        (const float*)d_in[12], (const float*)d_in[14],  // mp2_w1, mp2_w2
        (const float*)d_in[18], (const float*)d_in[19],  // gru_wih, gru_whh
        (const float*)d_in[28],                          // pq_w
        (const float*)d_in[22], (const float*)d_in[24], (const float*)d_in[26]); // op_w,c1_w,c2_w

    const size_t smem_bytes = (size_t)SMEM_FLOATS * sizeof(float);
    cudaFuncSetAttribute(mp_kernel, cudaFuncAttributeMaxDynamicSharedMemorySize, (int)smem_bytes);

    const int blocks = (B + WARPS - 1) / WARPS;
    mp_kernel<<<blocks, THREADS, smem_bytes>>>(
        (const float*)d_in[0], (const int*)d_in[1],
        (const float*)d_in[2], (const float*)d_in[3],
        (const float*)d_in[4], (const float*)d_in[5],     // ne_w, ne_b
        (const float*)d_in[7], (const float*)d_in[9],     // mp1_b1, mp1_b2
        (const float*)d_in[10], (const float*)d_in[11],   // n1_g, n1_b
        (const float*)d_in[13], (const float*)d_in[15],   // mp2_b1, mp2_b2
        (const float*)d_in[16], (const float*)d_in[17],   // n2_g, n2_b
        (const float*)d_in[20], (const float*)d_in[21],   // gru_bih, gru_bhh
        (const float*)d_in[23], (const float*)d_in[25], (const float*)d_in[27], // op_b, c1_b, c2_b
        (const float*)d_in[29],                           // pq_b
        (const float*)d_in[30], (const float*)d_in[31],   // pk_w, pk_b
        (float*)d_out, B);
}

// round 12
// speedup vs baseline: 1.0992x; 1.0992x over previous
#include <cuda_runtime.h>

#define WARPS 22
#define THREADS (WARPS * 32)
#define MAXN 20
#define CH 5

// ---- prep scratch (floats) ----
// staged once per block (both MLP blocks):
//   [0,4352)      mp1_w1 h-part padded [64][68]
//   [4352,8704)   mp1_w2 padded [64][68]
//   [8704,13056)  mp2_w1 h-part padded [64][68]
//   [13056,17408) mp2_w2 padded [64][68]
#define STAGE_FLOATS 17408
__device__ __align__(16) float g_stage[STAGE_FLOATS];
__device__ float2 g_w1bT2[2 * 64 * 32];  // msg-part of mp{1,2}_w1: [blk][k][lane]->{W[l][64+k],W[l+32][64+k]}
__device__ float2 g_wihT2[72 * 96];      // [k][gate][lane] -> {W[g*64+l][k], W[g*64+l+32][k]}
__device__ float2 g_whhT2[64 * 96];
__device__ float2 g_pqT2[64 * 32];
__device__ float  g_headsT[64 * 32];     // [k][t], t: 0-7 op, 8-17 c1, 18-27 c2, 28-31 zero

__global__ void prep_kernel(const float* __restrict__ mp1_w1, const float* __restrict__ mp1_w2,
                            const float* __restrict__ mp2_w1, const float* __restrict__ mp2_w2,
                            const float* __restrict__ gru_wih, const float* __restrict__ gru_whh,
                            const float* __restrict__ pq_w,
                            const float* __restrict__ op_w, const float* __restrict__ c1_w,
                            const float* __restrict__ c2_w)
{
    const int tid = blockIdx.x * blockDim.x + threadIdx.x;
    const int stride = gridDim.x * blockDim.x;
    for (int i = tid; i < 64 * 68; i += stride) {
        int r = i / 68, c = i % 68;
        g_stage[i]         = (c < 64) ? mp1_w1[r * 128 + c] : 0.f;  // h-part cols 0..63
        g_stage[4352 + i]  = (c < 64) ? mp1_w2[r * 64 + c] : 0.f;
        g_stage[8704 + i]  = (c < 64) ? mp2_w1[r * 128 + c] : 0.f;
        g_stage[13056 + i] = (c < 64) ? mp2_w2[r * 64 + c] : 0.f;
    }
    for (int i = tid; i < 64 * 32; i += stride) {
        int k = i / 32, l = i % 32;
        g_w1bT2[i]           = make_float2(mp1_w1[l * 128 + 64 + k], mp1_w1[(l + 32) * 128 + 64 + k]);
        g_w1bT2[64 * 32 + i] = make_float2(mp2_w1[l * 128 + 64 + k], mp2_w1[(l + 32) * 128 + 64 + k]);
        g_pqT2[i] = make_float2(pq_w[l * 64 + k], pq_w[(l + 32) * 64 + k]);
        float hv = 0.f;
        if (l < 8)       hv = op_w[l * 64 + k];
        else if (l < 18) hv = c1_w[(l - 8) * 64 + k];
        else if (l < 28) hv = c2_w[(l - 18) * 64 + k];
        g_headsT[i] = hv;
    }
    for (int i = tid; i < 72 * 96; i += stride) {
        int k = i / 96, g = (i % 96) / 32, l = i % 32;
        g_wihT2[i] = make_float2(gru_wih[(g * 64 + l) * 72 + k],
                                 gru_wih[(g * 64 + l + 32) * 72 + k]);
    }
    for (int i = tid; i < 64 * 96; i += stride) {
        int k = i / 96, g = (i % 96) / 32, l = i % 32;
        g_whhT2[i] = make_float2(gru_whh[(g * 64 + l) * 64 + k],
                                 gru_whh[(g * 64 + l + 32) * 64 + k]);
    }
}

__device__ __forceinline__ void fma4(float& acc, const float4 a, const float4 b) {
    acc = fmaf(a.x, b.x, acc);
    acc = fmaf(a.y, b.y, acc);
    acc = fmaf(a.z, b.z, acc);
    acc = fmaf(a.w, b.w, acc);
}

__device__ __forceinline__ float wsum(float v) {
#pragma unroll
    for (int o = 16; o > 0; o >>= 1) v += __shfl_xor_sync(0xffffffffu, v, o);
    return v;
}

// per-warp activation floats: sh(1280) su(320) sm(64) sa(64) sb(64) = 1792
#define ACT_FLOATS 1792
#define SMEM_FLOATS (STAGE_FLOATS + WARPS * ACT_FLOATS)   // 56832 floats = 227328 B

__global__ void __launch_bounds__(THREADS)
mp_kernel(const float* __restrict__ node_feats, const int* __restrict__ n_nodes,
          const float* __restrict__ rnn_state, const float* __restrict__ prev_op,
          const float* __restrict__ ne_w, const float* __restrict__ ne_b,
          const float* __restrict__ mp1_b1, const float* __restrict__ mp1_b2,
          const float* __restrict__ n1_g, const float* __restrict__ n1_b,
          const float* __restrict__ mp2_b1, const float* __restrict__ mp2_b2,
          const float* __restrict__ n2_g, const float* __restrict__ n2_b,
          const float* __restrict__ gru_bih, const float* __restrict__ gru_bhh,
          const float* __restrict__ op_b, const float* __restrict__ c1_b,
          const float* __restrict__ c2_b,
          const float* __restrict__ pq_b,
          const float* __restrict__ pk_w, const float* __restrict__ pk_b,
          float* __restrict__ out, int B)
{
    extern __shared__ float smem[];

    // ---- stage all MLP weights once (all threads), single barrier ----
    {
        const float4* src = (const float4*)g_stage;
        float4* dst = (float4*)smem;
        for (int i = threadIdx.x; i < STAGE_FLOATS / 4; i += THREADS) dst[i] = src[i];
    }
    __syncthreads();

    const int warp = threadIdx.x >> 5;
    const int lane = threadIdx.x & 31;
    const long b = (long)blockIdx.x * WARPS + warp;
    if (b >= B) return;   // safe: no block-wide barriers after this point

    const int o0 = lane, o1 = lane + 32;
    const int cnt = n_nodes[b];
    const float inv = 1.0f / (float)cnt;

    float* sh = smem + STAGE_FLOATS + warp * ACT_FLOATS;
    float* su = sh + 1280;
    float* sm = sh + 1600;
    float* sa = sh + 1664;
    float* sb = sh + 1728;

    const long OC1 = (long)B * 8;
    const long OC2 = (long)B * 18;
    const long OPTR = (long)B * 28;
    const long OST = (long)B * 48;

    // ---- load node feats (only cnt rows) into su (alias) ----
    {
        const float4* nf = (const float4*)(node_feats + b * (MAXN * 16));
        float4* d4 = (float4*)su;
        const int tot4 = cnt * 4;
        for (int i = lane; i < tot4; i += 32) d4[i] = nf[i];
    }
    const float st0 = rnn_state[b * 64 + o0];
    const float st1 = rnn_state[b * 64 + o1];
    sa[o0] = st0; sa[o1] = st1;
    const float4 pva = *(const float4*)(prev_op + b * 8);
    const float4 pvb = *(const float4*)(prev_op + b * 8 + 4);
    __syncwarp();

    // ---- encoder: h = nf @ ne_w^T + ne_b ; msg = masked mean ----
    float msg0 = 0.f, msg1 = 0.f;
    {
        float4 w0[4], w1[4];
#pragma unroll
        for (int kc = 0; kc < 4; kc++) {
            w0[kc] = *(const float4*)(ne_w + o0 * 16 + kc * 4);
            w1[kc] = *(const float4*)(ne_w + o1 * 16 + kc * 4);
        }
        const float nb0 = ne_b[o0], nb1 = ne_b[o1];
#pragma unroll
        for (int c = 0; c < 4; c++) {
            const int base = c * CH;
            if (base < cnt) {
                float a0[CH], a1[CH];
#pragma unroll
                for (int i = 0; i < CH; i++) { a0[i] = nb0; a1[i] = nb1; }
#pragma unroll
                for (int kc = 0; kc < 4; kc++) {
#pragma unroll
                    for (int i = 0; i < CH; i++) {
                        float4 xv = *(const float4*)(su + (base + i) * 16 + kc * 4);
                        fma4(a0[i], xv, w0[kc]);
                        fma4(a1[i], xv, w1[kc]);
                    }
                }
#pragma unroll
                for (int i = 0; i < CH; i++) {
                    const int n = base + i;
                    if (n < cnt) {
                        msg0 += a0[i]; msg1 += a1[i];
                        sh[n * 64 + o0] = a0[i];
                        sh[n * 64 + o1] = a1[i];
                    }
                }
            }
        }
    }
    msg0 *= inv; msg1 *= inv;
    __syncwarp();
    sm[o0] = msg0; sm[o1] = msg1;
    __syncwarp();

    // ---- two message-passing blocks (weights in smem, staged once) ----
#pragma unroll 1
    for (int blk = 0; blk < 2; blk++) {
        const float* W1s = smem + blk * 8704;
        const float* W2s = smem + blk * 8704 + 4352;
        const float* b1p = blk ? mp2_b1 : mp1_b1;
        const float* b2p = blk ? mp2_b2 : mp1_b2;
        const float* gp  = blk ? n2_g : n1_g;
        const float* lbp = blk ? n2_b : n1_b;

        // msg-dependent part of layer1 (row-invariant) via transposed global table
        float mm0 = b1p[o0], mm1 = b1p[o1];
        {
            const float2* wb = g_w1bT2 + blk * (64 * 32);
#pragma unroll 4
            for (int k = 0; k < 64; k++) {
                const float xm = sm[k];
                const float2 w = wb[k * 32 + lane];
                mm0 = fmaf(xm, w.x, mm0);
                mm1 = fmaf(xm, w.y, mm1);
            }
        }
        const float* w1r0 = W1s + o0 * 68;
        const float* w1r1 = W1s + o1 * 68;
        const float* w2r0 = W2s + o0 * 68;
        const float* w2r1 = W2s + o1 * 68;
        const float bb20 = b2p[o0], bb21 = b2p[o1];
        const float g0 = gp[o0], g1 = gp[o1];
        const float lb0 = lbp[o0], lb1 = lbp[o1];

        float nm0 = 0.f, nm1 = 0.f;
#pragma unroll
        for (int c = 0; c < 4; c++) {
            const int base = c * CH;
            if (base < cnt) {
                // layer1: u = relu(h @ W1a^T + mm)
                float a0[CH], a1[CH];
#pragma unroll
                for (int i = 0; i < CH; i++) { a0[i] = mm0; a1[i] = mm1; }
#pragma unroll
                for (int kc = 0; kc < 16; kc++) {
                    float4 wa = *(const float4*)(w1r0 + kc * 4);
                    float4 wb = *(const float4*)(w1r1 + kc * 4);
#pragma unroll
                    for (int i = 0; i < CH; i++) {
                        float4 xv = *(const float4*)(sh + (base + i) * 64 + kc * 4);
                        fma4(a0[i], xv, wa);
                        fma4(a1[i], xv, wb);
                    }
                }
#pragma unroll
                for (int i = 0; i < CH; i++) {
                    su[i * 64 + o0] = fmaxf(a0[i], 0.f);
                    su[i * 64 + o1] = fmaxf(a1[i], 0.f);
                }
                __syncwarp();
                // layer2 + residual + LN + mask
                float v0[CH], v1[CH];
#pragma unroll
                for (int i = 0; i < CH; i++) { v0[i] = bb20; v1[i] = bb21; }
#pragma unroll
                for (int kc = 0; kc < 16; kc++) {
                    float4 wa = *(const float4*)(w2r0 + kc * 4);
                    float4 wb = *(const float4*)(w2r1 + kc * 4);
#pragma unroll
                    for (int i = 0; i < CH; i++) {
                        float4 xv = *(const float4*)(su + i * 64 + kc * 4);
                        fma4(v0[i], xv, wa);
                        fma4(v1[i], xv, wb);
                    }
                }
#pragma unroll
                for (int i = 0; i < CH; i++) {
                    const int n = base + i;
                    if (n < cnt) {
                        float x0 = v0[i] + sh[n * 64 + o0];
                        float x1v = v1[i] + sh[n * 64 + o1];
                        float mu = wsum(x0 + x1v) * (1.0f / 64.0f);
                        float d0 = x0 - mu, d1 = x1v - mu;
                        float var = wsum(d0 * d0 + d1 * d1) * (1.0f / 64.0f);
                        float rs = rsqrtf(var + 1e-5f);
                        float h0 = d0 * rs * g0 + lb0;
                        float h1 = d1 * rs * g1 + lb1;
                        nm0 += h0; nm1 += h1;
                        sh[n * 64 + o0] = h0;
                        sh[n * 64 + o1] = h1;
                    }
                }
                __syncwarp();
            }
        }
        msg0 = nm0 * inv; msg1 = nm1 * inv;
        __syncwarp();
        sm[o0] = msg0; sm[o1] = msg1;
        __syncwarp();
    }

    // ---- GRU cell via transposed, lane-pair-packed weights (coalesced) ----
    float gir0 = gru_bih[o0],       gir1 = gru_bih[o1];
    float giz0 = gru_bih[64 + o0],  giz1 = gru_bih[64 + o1];
    float gin0 = gru_bih[128 + o0], gin1 = gru_bih[128 + o1];
    float ghr0 = gru_bhh[o0],       ghr1 = gru_bhh[o1];
    float ghz0 = gru_bhh[64 + o0],  ghz1 = gru_bhh[64 + o1];
    float ghn0 = gru_bhh[128 + o0], ghn1 = gru_bhh[128 + o1];
#pragma unroll 4
    for (int k = 0; k < 64; k++) {
        const float xm = sm[k];
        const float2* wk = g_wihT2 + k * 96;
        const float2 wr = wk[lane];
        const float2 wz = wk[32 + lane];
        const float2 wn = wk[64 + lane];
        gir0 = fmaf(xm, wr.x, gir0); gir1 = fmaf(xm, wr.y, gir1);
        giz0 = fmaf(xm, wz.x, giz0); giz1 = fmaf(xm, wz.y, giz1);
        gin0 = fmaf(xm, wn.x, gin0); gin1 = fmaf(xm, wn.y, gin1);
        const float xs = sa[k];
        const float2* vk = g_whhT2 + k * 96;
        const float2 vr = vk[lane];
        const float2 vz = vk[32 + lane];
        const float2 vn = vk[64 + lane];
        ghr0 = fmaf(xs, vr.x, ghr0); ghr1 = fmaf(xs, vr.y, ghr1);
        ghz0 = fmaf(xs, vz.x, ghz0); ghz1 = fmaf(xs, vz.y, ghz1);
        ghn0 = fmaf(xs, vn.x, ghn0); ghn1 = fmaf(xs, vn.y, ghn1);
    }
    {
        const float pv[8] = {pva.x, pva.y, pva.z, pva.w, pvb.x, pvb.y, pvb.z, pvb.w};
#pragma unroll
        for (int k = 0; k < 8; k++) {
            const float xp = pv[k];
            const float2* wk = g_wihT2 + (64 + k) * 96;
            const float2 wr = wk[lane];
            const float2 wz = wk[32 + lane];
            const float2 wn = wk[64 + lane];
            gir0 = fmaf(xp, wr.x, gir0); gir1 = fmaf(xp, wr.y, gir1);
            giz0 = fmaf(xp, wz.x, giz0); giz1 = fmaf(xp, wz.y, giz1);
            gin0 = fmaf(xp, wn.x, gin0); gin1 = fmaf(xp, wn.y, gin1);
        }
    }

    const float r0 = 1.0f / (1.0f + expf(-(gir0 + ghr0)));
    const float r1 = 1.0f / (1.0f + expf(-(gir1 + ghr1)));
    const float z0 = 1.0f / (1.0f + expf(-(giz0 + ghz0)));
    const float z1 = 1.0f / (1.0f + expf(-(giz1 + ghz1)));
    const float nn0 = tanhf(gin0 + r0 * ghn0);
    const float nn1 = tanhf(gin1 + r1 * ghn1);
    const float ns0 = (1.0f - z0) * nn0 + z0 * st0;
    const float ns1 = (1.0f - z1) * nn1 + z1 * st1;

    out[OST + b * 64 + o0] = ns0;
    out[OST + b * 64 + o1] = ns1;
    sb[o0] = ns0; sb[o1] = ns1;
    __syncwarp();

    // ---- heads via transposed matrix (coalesced; one output per lane) ----
    {
        float hb = 0.f; long off = -1;
        if (lane < 8)       { hb = op_b[lane];      off = b * 8 + lane; }
        else if (lane < 18) { hb = c1_b[lane - 8];  off = OC1 + b * 10 + (lane - 8); }
        else if (lane < 28) { hb = c2_b[lane - 18]; off = OC2 + b * 10 + (lane - 18); }
        float acc = hb;
#pragma unroll 4
        for (int k = 0; k < 64; k++) acc = fmaf(sb[k], g_headsT[k * 32 + lane], acc);
        if (off >= 0) out[off] = acc;
    }

    // ---- query via transposed pq, then qa = pk_w^T @ q ----
    float q0 = pq_b[o0], q1 = pq_b[o1];
#pragma unroll 4
    for (int k = 0; k < 64; k++) {
        const float xv = sb[k];
        const float2 w = g_pqT2[k * 32 + lane];
        q0 = fmaf(xv, w.x, q0); q1 = fmaf(xv, w.y, q1);
    }
    __syncwarp();
    sa[o0] = q0; sa[o1] = q1;
    __syncwarp();

    float qa0 = 0.f, qa1 = 0.f;
#pragma unroll 8
    for (int o = 0; o < 64; o++) {
        const float qv = sa[o];
        qa0 = fmaf(qv, pk_w[o * 64 + o0], qa0);
        qa1 = fmaf(qv, pk_w[o * 64 + o1], qa1);
    }
    const float qb = wsum(q0 * pk_b[o0] + q1 * pk_b[o1]);

    // ---- pointer logits ----
    for (int n = 0; n < cnt; n++) {
        float p = sh[n * 64 + o0] * qa0 + sh[n * 64 + o1] * qa1;
        float val = wsum(p) + qb;
        if (lane == 0) out[OPTR + b * 20 + n] = val;
    }
    for (int n = cnt + lane; n < MAXN; n += 32) out[OPTR + b * 20 + n] = -1e9f;
}

extern "C" void kernel_launch(void* const* d_in, const int* in_sizes, int n_in,
                              void* d_out, int out_size) {
    const int B = in_sizes[1];  // n_nodes element count

    prep_kernel<<<64, 256>>>(
        (const float*)d_in[6],  (const float*)d_in[8],   // mp1_w1, mp1_w2
        (const float*)d_in[12], (const float*)d_in[14],  // mp2_w1, mp2_w2
        (const float*)d_in[18], (const float*)d_in[19],  // gru_wih, gru_whh
        (const float*)d_in[28],                          // pq_w
        (const float*)d_in[22], (const float*)d_in[24], (const float*)d_in[26]); // op_w,c1_w,c2_w

    const size_t smem_bytes = (size_t)SMEM_FLOATS * sizeof(float);
    cudaFuncSetAttribute(mp_kernel, cudaFuncAttributeMaxDynamicSharedMemorySize, (int)smem_bytes);

    const int blocks = (B + WARPS - 1) / WARPS;
    mp_kernel<<<blocks, THREADS, smem_bytes>>>(
        (const float*)d_in[0], (const int*)d_in[1],
        (const float*)d_in[2], (const float*)d_in[3],
        (const float*)d_in[4], (const float*)d_in[5],     // ne_w, ne_b
        (const float*)d_in[7], (const float*)d_in[9],     // mp1_b1, mp1_b2
        (const float*)d_in[10], (const float*)d_in[11],   // n1_g, n1_b
        (const float*)d_in[13], (const float*)d_in[15],   // mp2_b1, mp2_b2
        (const float*)d_in[16], (const float*)d_in[17],   // n2_g, n2_b
        (const float*)d_in[20], (const float*)d_in[21],   // gru_bih, gru_bhh
        (const float*)d_in[23], (const float*)d_in[25], (const float*)d_in[27], // op_b, c1_b, c2_b
        (const float*)d_in[29],                           // pq_b
        (const float*)d_in[30], (const float*)d_in[31],   // pk_w, pk_b
        (float*)d_out, B);
}

// round 14
// speedup vs baseline: 1.4439x; 1.3136x over previous
#include <cuda_runtime.h>

#define WARPS 22
#define THREADS (WARPS * 32)
#define MAXN 20
#define CH 5
#define MAXB 65536

// ---- prep scratch (floats) ----
#define STAGE_FLOATS 17408
__device__ __align__(16) float g_stage[STAGE_FLOATS];
__device__ float2 g_w1bT2[2 * 64 * 32];
__device__ float2 g_wihT2[72 * 96];
__device__ float2 g_whhT2[64 * 96];
__device__ float2 g_pqT2[64 * 32];
__device__ float  g_headsT[64 * 32];
// ---- cnt-sort scratch ----
__device__ int g_perm[MAXB];
__device__ int g_binoff[MAXN + 2];
__device__ int g_bincur[MAXN + 2];

__global__ void sort_zero() {
    if (threadIdx.x <= MAXN + 1) { g_binoff[threadIdx.x] = 0; g_bincur[threadIdx.x] = 0; }
}
__global__ void sort_count(const int* __restrict__ n_nodes, int B) {
    int i = blockIdx.x * blockDim.x + threadIdx.x;
    if (i < B) atomicAdd(&g_binoff[n_nodes[i]], 1);
}
__global__ void sort_scan() {
    if (threadIdx.x == 0) {
        int acc = 0;
        for (int c = 1; c <= MAXN; c++) { int v = g_binoff[c]; g_binoff[c] = acc; g_bincur[c] = acc; acc += v; }
    }
}
__global__ void sort_scatter(const int* __restrict__ n_nodes, int B) {
    int i = blockIdx.x * blockDim.x + threadIdx.x;
    if (i < B) {
        int pos = atomicAdd(&g_bincur[n_nodes[i]], 1);
        g_perm[pos] = i;
    }
}

__global__ void prep_kernel(const float* __restrict__ mp1_w1, const float* __restrict__ mp1_w2,
                            const float* __restrict__ mp2_w1, const float* __restrict__ mp2_w2,
                            const float* __restrict__ gru_wih, const float* __restrict__ gru_whh,
                            const float* __restrict__ pq_w,
                            const float* __restrict__ op_w, const float* __restrict__ c1_w,
                            const float* __restrict__ c2_w)
{
    const int tid = blockIdx.x * blockDim.x + threadIdx.x;
    const int stride = gridDim.x * blockDim.x;
    for (int i = tid; i < 64 * 68; i += stride) {
        int r = i / 68, c = i % 68;
        g_stage[i]         = (c < 64) ? mp1_w1[r * 128 + c] : 0.f;
        g_stage[4352 + i]  = (c < 64) ? mp1_w2[r * 64 + c] : 0.f;
        g_stage[8704 + i]  = (c < 64) ? mp2_w1[r * 128 + c] : 0.f;
        g_stage[13056 + i] = (c < 64) ? mp2_w2[r * 64 + c] : 0.f;
    }
    for (int i = tid; i < 64 * 32; i += stride) {
        int k = i / 32, l = i % 32;
        g_w1bT2[i]           = make_float2(mp1_w1[l * 128 + 64 + k], mp1_w1[(l + 32) * 128 + 64 + k]);
        g_w1bT2[64 * 32 + i] = make_float2(mp2_w1[l * 128 + 64 + k], mp2_w1[(l + 32) * 128 + 64 + k]);
        g_pqT2[i] = make_float2(pq_w[l * 64 + k], pq_w[(l + 32) * 64 + k]);
        float hv = 0.f;
        if (l < 8)       hv = op_w[l * 64 + k];
        else if (l < 18) hv = c1_w[(l - 8) * 64 + k];
        else if (l < 28) hv = c2_w[(l - 18) * 64 + k];
        g_headsT[i] = hv;
    }
    for (int i = tid; i < 72 * 96; i += stride) {
        int k = i / 96, g = (i % 96) / 32, l = i % 32;
        g_wihT2[i] = make_float2(gru_wih[(g * 64 + l) * 72 + k],
                                 gru_wih[(g * 64 + l + 32) * 72 + k]);
    }
    for (int i = tid; i < 64 * 96; i += stride) {
        int k = i / 96, g = (i % 96) / 32, l = i % 32;
        g_whhT2[i] = make_float2(gru_whh[(g * 64 + l) * 64 + k],
                                 gru_whh[(g * 64 + l + 32) * 64 + k]);
    }
}

__device__ __forceinline__ void fma4(float& acc, const float4 a, const float4 b) {
    acc = fmaf(a.x, b.x, acc);
    acc = fmaf(a.y, b.y, acc);
    acc = fmaf(a.z, b.z, acc);
    acc = fmaf(a.w, b.w, acc);
}

__device__ __forceinline__ float wsum(float v) {
#pragma unroll
    for (int o = 16; o > 0; o >>= 1) v += __shfl_xor_sync(0xffffffffu, v, o);
    return v;
}

#define ACT_FLOATS 1792
#define SMEM_FLOATS (STAGE_FLOATS + WARPS * ACT_FLOATS)   // 227328 B

__global__ void __launch_bounds__(THREADS)
mp_kernel(const float* __restrict__ node_feats, const int* __restrict__ n_nodes,
          const float* __restrict__ rnn_state, const float* __restrict__ prev_op,
          const float* __restrict__ ne_w, const float* __restrict__ ne_b,
          const float* __restrict__ mp1_b1, const float* __restrict__ mp1_b2,
          const float* __restrict__ n1_g, const float* __restrict__ n1_b,
          const float* __restrict__ mp2_b1, const float* __restrict__ mp2_b2,
          const float* __restrict__ n2_g, const float* __restrict__ n2_b,
          const float* __restrict__ gru_bih, const float* __restrict__ gru_bhh,
          const float* __restrict__ op_b, const float* __restrict__ c1_b,
          const float* __restrict__ c2_b,
          const float* __restrict__ pq_b,
          const float* __restrict__ pk_w, const float* __restrict__ pk_b,
          float* __restrict__ out, int B)
{
    extern __shared__ float smem[];

    // ---- stage all MLP weights once (all threads), single barrier ----
    {
        const float4* src = (const float4*)g_stage;
        float4* dst = (float4*)smem;
        for (int i = threadIdx.x; i < STAGE_FLOATS / 4; i += THREADS) dst[i] = src[i];
    }
    __syncthreads();

    const int warp = threadIdx.x >> 5;
    const int lane = threadIdx.x & 31;
    const int slot = blockIdx.x * WARPS + warp;
    if (slot >= B) return;   // safe: no block-wide barriers after this point
    const long b = g_perm[slot];   // cnt-sorted mapping: warps in a block share similar cnt

    const int o0 = lane, o1 = lane + 32;
    const int cnt = n_nodes[b];
    const float inv = 1.0f / (float)cnt;

    float* sh = smem + STAGE_FLOATS + warp * ACT_FLOATS;
    float* su = sh + 1280;
    float* sm = sh + 1600;
    float* sa = sh + 1664;
    float* sb = sh + 1728;

    const long OC1 = (long)B * 8;
    const long OC2 = (long)B * 18;
    const long OPTR = (long)B * 28;
    const long OST = (long)B * 48;

    // ---- load node feats (only cnt rows) into su (alias) ----
    {
        const float4* nf = (const float4*)(node_feats + b * (MAXN * 16));
        float4* d4 = (float4*)su;
        const int tot4 = cnt * 4;
        for (int i = lane; i < tot4; i += 32) d4[i] = nf[i];
    }
    const float st0 = rnn_state[b * 64 + o0];
    const float st1 = rnn_state[b * 64 + o1];
    sa[o0] = st0; sa[o1] = st1;
    const float4 pva = *(const float4*)(prev_op + b * 8);
    const float4 pvb = *(const float4*)(prev_op + b * 8 + 4);
    __syncwarp();

    // ---- encoder: h = nf @ ne_w^T + ne_b ; msg = masked mean ----
    float msg0 = 0.f, msg1 = 0.f;
    {
        float4 w0[4], w1[4];
#pragma unroll
        for (int kc = 0; kc < 4; kc++) {
            w0[kc] = *(const float4*)(ne_w + o0 * 16 + kc * 4);
            w1[kc] = *(const float4*)(ne_w + o1 * 16 + kc * 4);
        }
        const float nb0 = ne_b[o0], nb1 = ne_b[o1];
#pragma unroll
        for (int c = 0; c < 4; c++) {
            const int base = c * CH;
            if (base < cnt) {
                float a0[CH], a1[CH];
#pragma unroll
                for (int i = 0; i < CH; i++) { a0[i] = nb0; a1[i] = nb1; }
#pragma unroll
                for (int kc = 0; kc < 4; kc++) {
#pragma unroll
                    for (int i = 0; i < CH; i++) {
                        float4 xv = *(const float4*)(su + (base + i) * 16 + kc * 4);
                        fma4(a0[i], xv, w0[kc]);
                        fma4(a1[i], xv, w1[kc]);
                    }
                }
#pragma unroll
                for (int i = 0; i < CH; i++) {
                    const int n = base + i;
                    if (n < cnt) {
                        msg0 += a0[i]; msg1 += a1[i];
                        sh[n * 64 + o0] = a0[i];
                        sh[n * 64 + o1] = a1[i];
                    }
                }
            }
        }
    }
    msg0 *= inv; msg1 *= inv;
    __syncwarp();
    sm[o0] = msg0; sm[o1] = msg1;
    __syncwarp();

    // ---- two message-passing blocks (weights in smem, staged once) ----
#pragma unroll 1
    for (int blk = 0; blk < 2; blk++) {
        const float* W1s = smem + blk * 8704;
        const float* W2s = smem + blk * 8704 + 4352;
        const float* b1p = blk ? mp2_b1 : mp1_b1;
        const float* b2p = blk ? mp2_b2 : mp1_b2;
        const float* gp  = blk ? n2_g : n1_g;
        const float* lbp = blk ? n2_b : n1_b;

        // msg-dependent part of layer1 (row-invariant) via transposed global table
        float mm0 = b1p[o0], mm1 = b1p[o1];
        {
            const float2* wb = g_w1bT2 + blk * (64 * 32);
#pragma unroll 4
            for (int k = 0; k < 64; k++) {
                const float xm = sm[k];
                const float2 w = wb[k * 32 + lane];
                mm0 = fmaf(xm, w.x, mm0);
                mm1 = fmaf(xm, w.y, mm1);
            }
        }
        const float* w1r0 = W1s + o0 * 68;
        const float* w1r1 = W1s + o1 * 68;
        const float* w2r0 = W2s + o0 * 68;
        const float* w2r1 = W2s + o1 * 68;
        const float bb20 = b2p[o0], bb21 = b2p[o1];
        const float g0 = gp[o0], g1 = gp[o1];
        const float lb0 = lbp[o0], lb1 = lbp[o1];

        float nm0 = 0.f, nm1 = 0.f;
#pragma unroll
        for (int c = 0; c < 4; c++) {
            const int base = c * CH;
            if (base < cnt) {
                // layer1: u = relu(h @ W1a^T + mm)
                float a0[CH], a1[CH];
#pragma unroll
                for (int i = 0; i < CH; i++) { a0[i] = mm0; a1[i] = mm1; }
#pragma unroll
                for (int kc = 0; kc < 16; kc++) {
                    float4 wa = *(const float4*)(w1r0 + kc * 4);
                    float4 wb = *(const float4*)(w1r1 + kc * 4);
#pragma unroll
                    for (int i = 0; i < CH; i++) {
                        float4 xv = *(const float4*)(sh + (base + i) * 64 + kc * 4);
                        fma4(a0[i], xv, wa);
                        fma4(a1[i], xv, wb);
                    }
                }
#pragma unroll
                for (int i = 0; i < CH; i++) {
                    su[i * 64 + o0] = fmaxf(a0[i], 0.f);
                    su[i * 64 + o1] = fmaxf(a1[i], 0.f);
                }
                __syncwarp();
                // layer2 + residual + LN + mask
                float v0[CH], v1[CH];
#pragma unroll
                for (int i = 0; i < CH; i++) { v0[i] = bb20; v1[i] = bb21; }
#pragma unroll
                for (int kc = 0; kc < 16; kc++) {
                    float4 wa = *(const float4*)(w2r0 + kc * 4);
                    float4 wb = *(const float4*)(w2r1 + kc * 4);
#pragma unroll
                    for (int i = 0; i < CH; i++) {
                        float4 xv = *(const float4*)(su + i * 64 + kc * 4);
                        fma4(v0[i], xv, wa);
                        fma4(v1[i], xv, wb);
                    }
                }
#pragma unroll
                for (int i = 0; i < CH; i++) {
                    const int n = base + i;
                    if (n < cnt) {
                        float x0 = v0[i] + sh[n * 64 + o0];
                        float x1v = v1[i] + sh[n * 64 + o1];
                        float mu = wsum(x0 + x1v) * (1.0f / 64.0f);
                        float d0 = x0 - mu, d1 = x1v - mu;
                        float var = wsum(d0 * d0 + d1 * d1) * (1.0f / 64.0f);
                        float rs = rsqrtf(var + 1e-5f);
                        float h0 = d0 * rs * g0 + lb0;
                        float h1 = d1 * rs * g1 + lb1;
                        nm0 += h0; nm1 += h1;
                        sh[n * 64 + o0] = h0;
                        sh[n * 64 + o1] = h1;
                    }
                }
                __syncwarp();
            }
        }
        msg0 = nm0 * inv; msg1 = nm1 * inv;
        __syncwarp();
        sm[o0] = msg0; sm[o1] = msg1;
        __syncwarp();
    }

    // ---- GRU cell via transposed, lane-pair-packed weights (coalesced) ----
    float gir0 = gru_bih[o0],       gir1 = gru_bih[o1];
    float giz0 = gru_bih[64 + o0],  giz1 = gru_bih[64 + o1];
    float gin0 = gru_bih[128 + o0], gin1 = gru_bih[128 + o1];
    float ghr0 = gru_bhh[o0],       ghr1 = gru_bhh[o1];
    float ghz0 = gru_bhh[64 + o0],  ghz1 = gru_bhh[64 + o1];
    float ghn0 = gru_bhh[128 + o0], ghn1 = gru_bhh[128 + o1];
#pragma unroll 4
    for (int k = 0; k < 64; k++) {
        const float xm = sm[k];
        const float2* wk = g_wihT2 + k * 96;
        const float2 wr = wk[lane];
        const float2 wz = wk[32 + lane];
        const float2 wn = wk[64 + lane];
        gir0 = fmaf(xm, wr.x, gir0); gir1 = fmaf(xm, wr.y, gir1);
        giz0 = fmaf(xm, wz.x, giz0); giz1 = fmaf(xm, wz.y, giz1);
        gin0 = fmaf(xm, wn.x, gin0); gin1 = fmaf(xm, wn.y, gin1);
        const float xs = sa[k];
        const float2* vk = g_whhT2 + k * 96;
        const float2 vr = vk[lane];
        const float2 vz = vk[32 + lane];
        const float2 vn = vk[64 + lane];
        ghr0 = fmaf(xs, vr.x, ghr0); ghr1 = fmaf(xs, vr.y, ghr1);
        ghz0 = fmaf(xs, vz.x, ghz0); ghz1 = fmaf(xs, vz.y, ghz1);
        ghn0 = fmaf(xs, vn.x, ghn0); ghn1 = fmaf(xs, vn.y, ghn1);
    }
    {
        const float pv[8] = {pva.x, pva.y, pva.z, pva.w, pvb.x, pvb.y, pvb.z, pvb.w};
#pragma unroll
        for (int k = 0; k < 8; k++) {
            const float xp = pv[k];
            const float2* wk = g_wihT2 + (64 + k) * 96;
            const float2 wr = wk[lane];
            const float2 wz = wk[32 + lane];
            const float2 wn = wk[64 + lane];
            gir0 = fmaf(xp, wr.x, gir0); gir1 = fmaf(xp, wr.y, gir1);
            giz0 = fmaf(xp, wz.x, giz0); giz1 = fmaf(xp, wz.y, giz1);
            gin0 = fmaf(xp, wn.x, gin0); gin1 = fmaf(xp, wn.y, gin1);
        }
    }

    const float r0 = 1.0f / (1.0f + expf(-(gir0 + ghr0)));
    const float r1 = 1.0f / (1.0f + expf(-(gir1 + ghr1)));
    const float z0 = 1.0f / (1.0f + expf(-(giz0 + ghz0)));
    const float z1 = 1.0f / (1.0f + expf(-(giz1 + ghz1)));
    const float nn0 = tanhf(gin0 + r0 * ghn0);
    const float nn1 = tanhf(gin1 + r1 * ghn1);
    const float ns0 = (1.0f - z0) * nn0 + z0 * st0;
    const float ns1 = (1.0f - z1) * nn1 + z1 * st1;

    out[OST + b * 64 + o0] = ns0;
    out[OST + b * 64 + o1] = ns1;
    sb[o0] = ns0; sb[o1] = ns1;
    __syncwarp();

    // ---- heads via transposed matrix (coalesced; one output per lane) ----
    {
        float hb = 0.f; long off = -1;
        if (lane < 8)       { hb = op_b[lane];      off = b * 8 + lane; }
        else if (lane < 18) { hb = c1_b[lane - 8];  off = OC1 + b * 10 + (lane - 8); }
        else if (lane < 28) { hb = c2_b[lane - 18]; off = OC2 + b * 10 + (lane - 18); }
        float acc = hb;
#pragma unroll 4
        for (int k = 0; k < 64; k++) acc = fmaf(sb[k], g_headsT[k * 32 + lane], acc);
        if (off >= 0) out[off] = acc;
    }

    // ---- query via transposed pq, then qa = pk_w^T @ q ----
    float q0 = pq_b[o0], q1 = pq_b[o1];
#pragma unroll 4
    for (int k = 0; k < 64; k++) {
        const float xv = sb[k];
        const float2 w = g_pqT2[k * 32 + lane];
        q0 = fmaf(xv, w.x, q0); q1 = fmaf(xv, w.y, q1);
    }
    __syncwarp();
    sa[o0] = q0; sa[o1] = q1;
    __syncwarp();

    float qa0 = 0.f, qa1 = 0.f;
#pragma unroll 8
    for (int o = 0; o < 64; o++) {
        const float qv = sa[o];
        qa0 = fmaf(qv, pk_w[o * 64 + o0], qa0);
        qa1 = fmaf(qv, pk_w[o * 64 + o1], qa1);
    }
    const float qb = wsum(q0 * pk_b[o0] + q1 * pk_b[o1]);

    // ---- pointer logits ----
    for (int n = 0; n < cnt; n++) {
        float p = sh[n * 64 + o0] * qa0 + sh[n * 64 + o1] * qa1;
        float val = wsum(p) + qb;
        if (lane == 0) out[OPTR + b * 20 + n] = val;
    }
    for (int n = cnt + lane; n < MAXN; n += 32) out[OPTR + b * 20 + n] = -1e9f;
}

extern "C" void kernel_launch(void* const* d_in, const int* in_sizes, int n_in,
                              void* d_out, int out_size) {
    const int B = in_sizes[1];  // n_nodes element count
    const int* n_nodes = (const int*)d_in[1];

    // cnt-sort elements so warps within a block get similar node counts
    sort_zero<<<1, 32>>>();
    sort_count<<<(B + 255) / 256, 256>>>(n_nodes, B);
    sort_scan<<<1, 32>>>();
    sort_scatter<<<(B + 255) / 256, 256>>>(n_nodes, B);

    prep_kernel<<<64, 256>>>(
        (const float*)d_in[6],  (const float*)d_in[8],   // mp1_w1, mp1_w2
        (const float*)d_in[12], (const float*)d_in[14],  // mp2_w1, mp2_w2
        (const float*)d_in[18], (const float*)d_in[19],  // gru_wih, gru_whh
        (const float*)d_in[28],                          // pq_w
        (const float*)d_in[22], (const float*)d_in[24], (const float*)d_in[26]); // op_w,c1_w,c2_w

    const size_t smem_bytes = (size_t)SMEM_FLOATS * sizeof(float);
    cudaFuncSetAttribute(mp_kernel, cudaFuncAttributeMaxDynamicSharedMemorySize, (int)smem_bytes);

    const int blocks = (B + WARPS - 1) / WARPS;
    mp_kernel<<<blocks, THREADS, smem_bytes>>>(
        (const float*)d_in[0], (const int*)d_in[1],
        (const float*)d_in[2], (const float*)d_in[3],
        (const float*)d_in[4], (const float*)d_in[5],     // ne_w, ne_b
        (const float*)d_in[7], (const float*)d_in[9],     // mp1_b1, mp1_b2
        (const float*)d_in[10], (const float*)d_in[11],   // n1_g, n1_b
        (const float*)d_in[13], (const float*)d_in[15],   // mp2_b1, mp2_b2
        (const float*)d_in[16], (const float*)d_in[17],   // n2_g, n2_b
        (const float*)d_in[20], (const float*)d_in[21],   // gru_bih, gru_bhh
        (const float*)d_in[23], (const float*)d_in[25], (const float*)d_in[27], // op_b, c1_b, c2_b
        (const float*)d_in[29],                           // pq_b
        (const float*)d_in[30], (const float*)d_in[31],   // pk_w, pk_b
        (float*)d_out, B);
}

// round 15
// speedup vs baseline: 1.4825x; 1.0268x over previous
#include <cuda_runtime.h>

#define MAXN 20
#define CH 5
#define MAXB 65536

#define W_SMALL 25
#define W_BIG   22

// ---- prep scratch (floats) ----
#define STAGE_FLOATS 17408
__device__ __align__(16) float g_stage[STAGE_FLOATS];
__device__ float2 g_w1bT2[2 * 64 * 32];
__device__ float2 g_wihT2[72 * 96];
__device__ float2 g_whhT2[64 * 96];
__device__ float2 g_pqT2[64 * 32];
__device__ float  g_headsT[64 * 32];
// ---- cnt-sort scratch ----
__device__ int g_perm[MAXB];
__device__ int g_binoff[MAXN + 2];
__device__ int g_bincur[MAXN + 2];

__global__ void sort_zero() {
    if (threadIdx.x <= MAXN + 1) { g_binoff[threadIdx.x] = 0; g_bincur[threadIdx.x] = 0; }
}
__global__ void sort_count(const int* __restrict__ n_nodes, int B) {
    __shared__ int h[32];
    if (threadIdx.x < 32) h[threadIdx.x] = 0;
    __syncthreads();
    int i = blockIdx.x * blockDim.x + threadIdx.x;
    const int stride = gridDim.x * blockDim.x;
    for (; i < B; i += stride) atomicAdd(&h[n_nodes[i]], 1);
    __syncthreads();
    if (threadIdx.x < 32 && h[threadIdx.x]) atomicAdd(&g_binoff[threadIdx.x], h[threadIdx.x]);
}
__global__ void sort_scan() {
    if (threadIdx.x == 0) {
        int acc = 0;
        for (int c = 1; c <= MAXN; c++) { int v = g_binoff[c]; g_binoff[c] = acc; g_bincur[c] = acc; acc += v; }
    }
}
__global__ void sort_scatter(const int* __restrict__ n_nodes, int B) {
    __shared__ int h[32], base[32];
    if (threadIdx.x < 32) h[threadIdx.x] = 0;
    __syncthreads();
    const int i = blockIdx.x * blockDim.x + threadIdx.x;
    int c = 0, local = 0;
    if (i < B) { c = n_nodes[i]; local = atomicAdd(&h[c], 1); }
    __syncthreads();
    if (threadIdx.x < 32) {
        int n = h[threadIdx.x];
        base[threadIdx.x] = n ? atomicAdd(&g_bincur[threadIdx.x], n) : 0;
    }
    __syncthreads();
    if (i < B) g_perm[base[c] + local] = i;
}

__global__ void prep_kernel(const float* __restrict__ mp1_w1, const float* __restrict__ mp1_w2,
                            const float* __restrict__ mp2_w1, const float* __restrict__ mp2_w2,
                            const float* __restrict__ gru_wih, const float* __restrict__ gru_whh,
                            const float* __restrict__ pq_w,
                            const float* __restrict__ op_w, const float* __restrict__ c1_w,
                            const float* __restrict__ c2_w)
{
    const int tid = blockIdx.x * blockDim.x + threadIdx.x;
    const int stride = gridDim.x * blockDim.x;
    for (int i = tid; i < 64 * 68; i += stride) {
        int r = i / 68, c = i % 68;
        g_stage[i]         = (c < 64) ? mp1_w1[r * 128 + c] : 0.f;
        g_stage[4352 + i]  = (c < 64) ? mp1_w2[r * 64 + c] : 0.f;
        g_stage[8704 + i]  = (c < 64) ? mp2_w1[r * 128 + c] : 0.f;
        g_stage[13056 + i] = (c < 64) ? mp2_w2[r * 64 + c] : 0.f;
    }
    for (int i = tid; i < 64 * 32; i += stride) {
        int k = i / 32, l = i % 32;
        g_w1bT2[i]           = make_float2(mp1_w1[l * 128 + 64 + k], mp1_w1[(l + 32) * 128 + 64 + k]);
        g_w1bT2[64 * 32 + i] = make_float2(mp2_w1[l * 128 + 64 + k], mp2_w1[(l + 32) * 128 + 64 + k]);
        g_pqT2[i] = make_float2(pq_w[l * 64 + k], pq_w[(l + 32) * 64 + k]);
        float hv = 0.f;
        if (l < 8)       hv = op_w[l * 64 + k];
        else if (l < 18) hv = c1_w[(l - 8) * 64 + k];
        else if (l < 28) hv = c2_w[(l - 18) * 64 + k];
        g_headsT[i] = hv;
    }
    for (int i = tid; i < 72 * 96; i += stride) {
        int k = i / 96, g = (i % 96) / 32, l = i % 32;
        g_wihT2[i] = make_float2(gru_wih[(g * 64 + l) * 72 + k],
                                 gru_wih[(g * 64 + l + 32) * 72 + k]);
    }
    for (int i = tid; i < 64 * 96; i += stride) {
        int k = i / 96, g = (i % 96) / 32, l = i % 32;
        g_whhT2[i] = make_float2(gru_whh[(g * 64 + l) * 64 + k],
                                 gru_whh[(g * 64 + l + 32) * 64 + k]);
    }
}

__device__ __forceinline__ void fma4(float& acc, const float4 a, const float4 b) {
    acc = fmaf(a.x, b.x, acc);
    acc = fmaf(a.y, b.y, acc);
    acc = fmaf(a.z, b.z, acc);
    acc = fmaf(a.w, b.w, acc);
}

__device__ __forceinline__ float wsum(float v) {
#pragma unroll
    for (int o = 16; o > 0; o >>= 1) v += __shfl_xor_sync(0xffffffffu, v, o);
    return v;
}

// W = warps/block, SHN = max nodes held, MAXC = max chunk count, [CMIN,CMAX] cnt range
template <int W, int SHN, int MAXC, int CMIN, int CMAX>
__global__ void __launch_bounds__(W * 32)
mp_kernel(const float* __restrict__ node_feats, const int* __restrict__ n_nodes,
          const float* __restrict__ rnn_state, const float* __restrict__ prev_op,
          const float* __restrict__ ne_w, const float* __restrict__ ne_b,
          const float* __restrict__ mp1_b1, const float* __restrict__ mp1_b2,
          const float* __restrict__ n1_g, const float* __restrict__ n1_b,
          const float* __restrict__ mp2_b1, const float* __restrict__ mp2_b2,
          const float* __restrict__ n2_g, const float* __restrict__ n2_b,
          const float* __restrict__ gru_bih, const float* __restrict__ gru_bhh,
          const float* __restrict__ op_b, const float* __restrict__ c1_b,
          const float* __restrict__ c2_b,
          const float* __restrict__ pq_b,
          const float* __restrict__ pk_w, const float* __restrict__ pk_b,
          float* __restrict__ out, int B)
{
    extern __shared__ float smem[];
    constexpr int ACT = SHN * 64 + CH * 64 + 192;

    // ---- stage all MLP weights once (all threads), single barrier ----
    {
        const float4* src = (const float4*)g_stage;
        float4* dst = (float4*)smem;
        for (int i = threadIdx.x; i < STAGE_FLOATS / 4; i += W * 32) dst[i] = src[i];
    }
    __syncthreads();

    const int warp = threadIdx.x >> 5;
    const int lane = threadIdx.x & 31;
    const int slot = blockIdx.x * W + warp;
    if (slot >= B) return;   // safe: no block-wide barriers after this point
    const long b = g_perm[slot];

    const int o0 = lane, o1 = lane + 32;
    const int cnt = n_nodes[b];
    if (cnt < CMIN || cnt > CMAX) return;   // other kernel variant handles it
    const float inv = 1.0f / (float)cnt;

    float* sh = smem + STAGE_FLOATS + warp * ACT;
    float* su = sh + SHN * 64;
    float* sm = su + CH * 64;
    float* sa = sm + 64;
    float* sb = sa + 64;

    const long OC1 = (long)B * 8;
    const long OC2 = (long)B * 18;
    const long OPTR = (long)B * 28;
    const long OST = (long)B * 48;

    // ---- load node feats (only cnt rows) into su (alias) ----
    {
        const float4* nf = (const float4*)(node_feats + b * (MAXN * 16));
        float4* d4 = (float4*)su;
        const int tot4 = cnt * 4;
        for (int i = lane; i < tot4; i += 32) d4[i] = nf[i];
    }
    const float st0 = rnn_state[b * 64 + o0];
    const float st1 = rnn_state[b * 64 + o1];
    sa[o0] = st0; sa[o1] = st1;
    const float4 pva = *(const float4*)(prev_op + b * 8);
    const float4 pvb = *(const float4*)(prev_op + b * 8 + 4);
    __syncwarp();

    // ---- encoder: h = nf @ ne_w^T + ne_b ; msg = masked mean ----
    float msg0 = 0.f, msg1 = 0.f;
    {
        float4 w0[4], w1[4];
#pragma unroll
        for (int kc = 0; kc < 4; kc++) {
            w0[kc] = *(const float4*)(ne_w + o0 * 16 + kc * 4);
            w1[kc] = *(const float4*)(ne_w + o1 * 16 + kc * 4);
        }
        const float nb0 = ne_b[o0], nb1 = ne_b[o1];
#pragma unroll
        for (int c = 0; c < MAXC; c++) {
            const int base = c * CH;
            if (base < cnt) {
                float a0[CH], a1[CH];
#pragma unroll
                for (int i = 0; i < CH; i++) { a0[i] = nb0; a1[i] = nb1; }
#pragma unroll
                for (int kc = 0; kc < 4; kc++) {
#pragma unroll
                    for (int i = 0; i < CH; i++) {
                        float4 xv = *(const float4*)(su + (base + i) * 16 + kc * 4);
                        fma4(a0[i], xv, w0[kc]);
                        fma4(a1[i], xv, w1[kc]);
                    }
                }
#pragma unroll
                for (int i = 0; i < CH; i++) {
                    const int n = base + i;
                    if (n < cnt) {
                        msg0 += a0[i]; msg1 += a1[i];
                        sh[n * 64 + o0] = a0[i];
                        sh[n * 64 + o1] = a1[i];
                    }
                }
            }
        }
    }
    msg0 *= inv; msg1 *= inv;
    __syncwarp();
    sm[o0] = msg0; sm[o1] = msg1;
    __syncwarp();

    // ---- two message-passing blocks (weights in smem, staged once) ----
#pragma unroll 1
    for (int blk = 0; blk < 2; blk++) {
        const float* W1s = smem + blk * 8704;
        const float* W2s = smem + blk * 8704 + 4352;
        const float* b1p = blk ? mp2_b1 : mp1_b1;
        const float* b2p = blk ? mp2_b2 : mp1_b2;
        const float* gp  = blk ? n2_g : n1_g;
        const float* lbp = blk ? n2_b : n1_b;

        // msg-dependent part of layer1 (row-invariant) via transposed global table
        float mm0 = b1p[o0], mm1 = b1p[o1];
        {
            const float2* wb = g_w1bT2 + blk * (64 * 32);
#pragma unroll 4
            for (int k = 0; k < 64; k++) {
                const float xm = sm[k];
                const float2 w = wb[k * 32 + lane];
                mm0 = fmaf(xm, w.x, mm0);
                mm1 = fmaf(xm, w.y, mm1);
            }
        }
        const float* w1r0 = W1s + o0 * 68;
        const float* w1r1 = W1s + o1 * 68;
        const float* w2r0 = W2s + o0 * 68;
        const float* w2r1 = W2s + o1 * 68;
        const float bb20 = b2p[o0], bb21 = b2p[o1];
        const float g0 = gp[o0], g1 = gp[o1];
        const float lb0 = lbp[o0], lb1 = lbp[o1];

        float nm0 = 0.f, nm1 = 0.f;
#pragma unroll
        for (int c = 0; c < MAXC; c++) {
            const int base = c * CH;
            if (base < cnt) {
                // layer1: u = relu(h @ W1a^T + mm)
                float a0[CH], a1[CH];
#pragma unroll
                for (int i = 0; i < CH; i++) { a0[i] = mm0; a1[i] = mm1; }
#pragma unroll
                for (int kc = 0; kc < 16; kc++) {
                    float4 wa = *(const float4*)(w1r0 + kc * 4);
                    float4 wb = *(const float4*)(w1r1 + kc * 4);
#pragma unroll
                    for (int i = 0; i < CH; i++) {
                        float4 xv = *(const float4*)(sh + (base + i) * 64 + kc * 4);
                        fma4(a0[i], xv, wa);
                        fma4(a1[i], xv, wb);
                    }
                }
#pragma unroll
                for (int i = 0; i < CH; i++) {
                    su[i * 64 + o0] = fmaxf(a0[i], 0.f);
                    su[i * 64 + o1] = fmaxf(a1[i], 0.f);
                }
                __syncwarp();
                // layer2 + residual + LN + mask
                float v0[CH], v1[CH];
#pragma unroll
                for (int i = 0; i < CH; i++) { v0[i] = bb20; v1[i] = bb21; }
#pragma unroll
                for (int kc = 0; kc < 16; kc++) {
                    float4 wa = *(const float4*)(w2r0 + kc * 4);
                    float4 wb = *(const float4*)(w2r1 + kc * 4);
#pragma unroll
                    for (int i = 0; i < CH; i++) {
                        float4 xv = *(const float4*)(su + i * 64 + kc * 4);
                        fma4(v0[i], xv, wa);
                        fma4(v1[i], xv, wb);
                    }
                }
#pragma unroll
                for (int i = 0; i < CH; i++) {
                    const int n = base + i;
                    if (n < cnt) {
                        float x0 = v0[i] + sh[n * 64 + o0];
                        float x1v = v1[i] + sh[n * 64 + o1];
                        float mu = wsum(x0 + x1v) * (1.0f / 64.0f);
                        float d0 = x0 - mu, d1 = x1v - mu;
                        float var = wsum(d0 * d0 + d1 * d1) * (1.0f / 64.0f);
                        float rs = rsqrtf(var + 1e-5f);
                        float h0 = d0 * rs * g0 + lb0;
                        float h1 = d1 * rs * g1 + lb1;
                        nm0 += h0; nm1 += h1;
                        sh[n * 64 + o0] = h0;
                        sh[n * 64 + o1] = h1;
                    }
                }
                __syncwarp();
            }
        }
        msg0 = nm0 * inv; msg1 = nm1 * inv;
        __syncwarp();
        sm[o0] = msg0; sm[o1] = msg1;
        __syncwarp();
    }

    // ---- GRU cell via transposed, lane-pair-packed weights (coalesced) ----
    float gir0 = gru_bih[o0],       gir1 = gru_bih[o1];
    float giz0 = gru_bih[64 + o0],  giz1 = gru_bih[64 + o1];
    float gin0 = gru_bih[128 + o0], gin1 = gru_bih[128 + o1];
    float ghr0 = gru_bhh[o0],       ghr1 = gru_bhh[o1];
    float ghz0 = gru_bhh[64 + o0],  ghz1 = gru_bhh[64 + o1];
    float ghn0 = gru_bhh[128 + o0], ghn1 = gru_bhh[128 + o1];
#pragma unroll 4
    for (int k = 0; k < 64; k++) {
        const float xm = sm[k];
        const float2* wk = g_wihT2 + k * 96;
        const float2 wr = wk[lane];
        const float2 wz = wk[32 + lane];
        const float2 wn = wk[64 + lane];
        gir0 = fmaf(xm, wr.x, gir0); gir1 = fmaf(xm, wr.y, gir1);
        giz0 = fmaf(xm, wz.x, giz0); giz1 = fmaf(xm, wz.y, giz1);
        gin0 = fmaf(xm, wn.x, gin0); gin1 = fmaf(xm, wn.y, gin1);
        const float xs = sa[k];
        const float2* vk = g_whhT2 + k * 96;
        const float2 vr = vk[lane];
        const float2 vz = vk[32 + lane];
        const float2 vn = vk[64 + lane];
        ghr0 = fmaf(xs, vr.x, ghr0); ghr1 = fmaf(xs, vr.y, ghr1);
        ghz0 = fmaf(xs, vz.x, ghz0); ghz1 = fmaf(xs, vz.y, ghz1);
        ghn0 = fmaf(xs, vn.x, ghn0); ghn1 = fmaf(xs, vn.y, ghn1);
    }
    {
        const float pv[8] = {pva.x, pva.y, pva.z, pva.w, pvb.x, pvb.y, pvb.z, pvb.w};
#pragma unroll
        for (int k = 0; k < 8; k++) {
            const float xp = pv[k];
            const float2* wk = g_wihT2 + (64 + k) * 96;
            const float2 wr = wk[lane];
            const float2 wz = wk[32 + lane];
            const float2 wn = wk[64 + lane];
            gir0 = fmaf(xp, wr.x, gir0); gir1 = fmaf(xp, wr.y, gir1);
            giz0 = fmaf(xp, wz.x, giz0); giz1 = fmaf(xp, wz.y, giz1);
            gin0 = fmaf(xp, wn.x, gin0); gin1 = fmaf(xp, wn.y, gin1);
        }
    }

    const float r0 = 1.0f / (1.0f + expf(-(gir0 + ghr0)));
    const float r1 = 1.0f / (1.0f + expf(-(gir1 + ghr1)));
    const float z0 = 1.0f / (1.0f + expf(-(giz0 + ghz0)));
    const float z1 = 1.0f / (1.0f + expf(-(giz1 + ghz1)));
    const float nn0 = tanhf(gin0 + r0 * ghn0);
    const float nn1 = tanhf(gin1 + r1 * ghn1);
    const float ns0 = (1.0f - z0) * nn0 + z0 * st0;
    const float ns1 = (1.0f - z1) * nn1 + z1 * st1;

    out[OST + b * 64 + o0] = ns0;
    out[OST + b * 64 + o1] = ns1;
    sb[o0] = ns0; sb[o1] = ns1;
    __syncwarp();

    // ---- heads via transposed matrix (coalesced; one output per lane) ----
    {
        float hb = 0.f; long off = -1;
        if (lane < 8)       { hb = op_b[lane];      off = b * 8 + lane; }
        else if (lane < 18) { hb = c1_b[lane - 8];  off = OC1 + b * 10 + (lane - 8); }
        else if (lane < 28) { hb = c2_b[lane - 18]; off = OC2 + b * 10 + (lane - 18); }
        float acc = hb;
#pragma unroll 4
        for (int k = 0; k < 64; k++) acc = fmaf(sb[k], g_headsT[k * 32 + lane], acc);
        if (off >= 0) out[off] = acc;
    }

    // ---- query via transposed pq, then qa = pk_w^T @ q ----
    float q0 = pq_b[o0], q1 = pq_b[o1];
#pragma unroll 4
    for (int k = 0; k < 64; k++) {
        const float xv = sb[k];
        const float2 w = g_pqT2[k * 32 + lane];
        q0 = fmaf(xv, w.x, q0); q1 = fmaf(xv, w.y, q1);
    }
    __syncwarp();
    sa[o0] = q0; sa[o1] = q1;
    __syncwarp();

    float qa0 = 0.f, qa1 = 0.f;
#pragma unroll 8
    for (int o = 0; o < 64; o++) {
        const float qv = sa[o];
        qa0 = fmaf(qv, pk_w[o * 64 + o0], qa0);
        qa1 = fmaf(qv, pk_w[o * 64 + o1], qa1);
    }
    const float qb = wsum(q0 * pk_b[o0] + q1 * pk_b[o1]);

    // ---- pointer logits ----
    for (int n = 0; n < cnt; n++) {
        float p = sh[n * 64 + o0] * qa0 + sh[n * 64 + o1] * qa1;
        float val = wsum(p) + qb;
        if (lane == 0) out[OPTR + b * 20 + n] = val;
    }
    for (int n = cnt + lane; n < MAXN; n += 32) out[OPTR + b * 20 + n] = -1e9f;
}

#define ACT_OF(SHN) ((SHN) * 64 + CH * 64 + 192)

extern "C" void kernel_launch(void* const* d_in, const int* in_sizes, int n_in,
                              void* d_out, int out_size) {
    const int B = in_sizes[1];  // n_nodes element count
    const int* n_nodes = (const int*)d_in[1];

    // cnt-sort elements so warps within a block get similar node counts
    sort_zero<<<1, 32>>>();
    sort_count<<<128, 256>>>(n_nodes, B);
    sort_scan<<<1, 32>>>();
    sort_scatter<<<(B + 255) / 256, 256>>>(n_nodes, B);

    prep_kernel<<<64, 256>>>(
        (const float*)d_in[6],  (const float*)d_in[8],   // mp1_w1, mp1_w2
        (const float*)d_in[12], (const float*)d_in[14],  // mp2_w1, mp2_w2
        (const float*)d_in[18], (const float*)d_in[19],  // gru_wih, gru_whh
        (const float*)d_in[28],                          // pq_w
        (const float*)d_in[22], (const float*)d_in[24], (const float*)d_in[26]); // op_w,c1_w,c2_w

    auto kern_small = mp_kernel<W_SMALL, 10, 2, 1, 10>;
    auto kern_big   = mp_kernel<W_BIG,   20, 4, 11, 20>;

    const size_t smem_small = (size_t)(STAGE_FLOATS + W_SMALL * ACT_OF(10)) * sizeof(float);
    const size_t smem_big   = (size_t)(STAGE_FLOATS + W_BIG   * ACT_OF(20)) * sizeof(float);
    cudaFuncSetAttribute(kern_small, cudaFuncAttributeMaxDynamicSharedMemorySize, (int)smem_small);
    cudaFuncSetAttribute(kern_big,   cudaFuncAttributeMaxDynamicSharedMemorySize, (int)smem_big);

#define MP_ARGS \
        (const float*)d_in[0], (const int*)d_in[1], \
        (const float*)d_in[2], (const float*)d_in[3], \
        (const float*)d_in[4], (const float*)d_in[5], \
        (const float*)d_in[7], (const float*)d_in[9], \
        (const float*)d_in[10], (const float*)d_in[11], \
        (const float*)d_in[13], (const float*)d_in[15], \
        (const float*)d_in[16], (const float*)d_in[17], \
        (const float*)d_in[20], (const float*)d_in[21], \
        (const float*)d_in[23], (const float*)d_in[25], (const float*)d_in[27], \
        (const float*)d_in[29], \
        (const float*)d_in[30], (const float*)d_in[31], \
        (float*)d_out, B

    kern_small<<<(B + W_SMALL - 1) / W_SMALL, W_SMALL * 32, smem_small>>>(MP_ARGS);
    kern_big  <<<(B + W_BIG   - 1) / W_BIG,   W_BIG   * 32, smem_big  >>>(MP_ARGS);
#undef MP_ARGS
}

// round 16
// speedup vs baseline: 1.5376x; 1.0371x over previous
#include <cuda_runtime.h>

#define MAXN 20
#define CH 5
#define MAXB 65536

#define W_SMALL 22
#define W_BIG   22

// ---- prep scratch (floats) ----
#define STAGE_FLOATS 17408
__device__ __align__(16) float g_stage[STAGE_FLOATS];
__device__ float2 g_w1bT2[2 * 64 * 32];
__device__ float2 g_wihT2[72 * 96];
__device__ float2 g_whhT2[64 * 96];
__device__ float2 g_pqT2[64 * 32];
__device__ float  g_headsT[64 * 32];
// ---- cnt-sort scratch ----
__device__ int g_perm[MAXB];
__device__ int g_binoff[MAXN + 2];
__device__ int g_bincur[MAXN + 2];

__global__ void sort_zero() {
    if (threadIdx.x <= MAXN + 1) { g_binoff[threadIdx.x] = 0; g_bincur[threadIdx.x] = 0; }
}
__global__ void sort_count(const int* __restrict__ n_nodes, int B) {
    __shared__ int h[32];
    if (threadIdx.x < 32) h[threadIdx.x] = 0;
    __syncthreads();
    int i = blockIdx.x * blockDim.x + threadIdx.x;
    const int stride = gridDim.x * blockDim.x;
    for (; i < B; i += stride) atomicAdd(&h[n_nodes[i]], 1);
    __syncthreads();
    if (threadIdx.x < 32 && h[threadIdx.x]) atomicAdd(&g_binoff[threadIdx.x], h[threadIdx.x]);
}
__global__ void sort_scan() {
    if (threadIdx.x == 0) {
        int acc = 0;
        for (int c = 1; c <= MAXN; c++) { int v = g_binoff[c]; g_binoff[c] = acc; g_bincur[c] = acc; acc += v; }
    }
}
__global__ void sort_scatter(const int* __restrict__ n_nodes, int B) {
    __shared__ int h[32], base[32];
    if (threadIdx.x < 32) h[threadIdx.x] = 0;
    __syncthreads();
    const int i = blockIdx.x * blockDim.x + threadIdx.x;
    int c = 0, local = 0;
    if (i < B) { c = n_nodes[i]; local = atomicAdd(&h[c], 1); }
    __syncthreads();
    if (threadIdx.x < 32) {
        int n = h[threadIdx.x];
        base[threadIdx.x] = n ? atomicAdd(&g_bincur[threadIdx.x], n) : 0;
    }
    __syncthreads();
    if (i < B) g_perm[base[c] + local] = i;
}

__global__ void prep_kernel(const float* __restrict__ mp1_w1, const float* __restrict__ mp1_w2,
                            const float* __restrict__ mp2_w1, const float* __restrict__ mp2_w2,
                            const float* __restrict__ gru_wih, const float* __restrict__ gru_whh,
                            const float* __restrict__ pq_w,
                            const float* __restrict__ op_w, const float* __restrict__ c1_w,
                            const float* __restrict__ c2_w)
{
    const int tid = blockIdx.x * blockDim.x + threadIdx.x;
    const int stride = gridDim.x * blockDim.x;
    for (int i = tid; i < 64 * 68; i += stride) {
        int r = i / 68, c = i % 68;
        g_stage[i]         = (c < 64) ? mp1_w1[r * 128 + c] : 0.f;
        g_stage[4352 + i]  = (c < 64) ? mp1_w2[r * 64 + c] : 0.f;
        g_stage[8704 + i]  = (c < 64) ? mp2_w1[r * 128 + c] : 0.f;
        g_stage[13056 + i] = (c < 64) ? mp2_w2[r * 64 + c] : 0.f;
    }
    for (int i = tid; i < 64 * 32; i += stride) {
        int k = i / 32, l = i % 32;
        g_w1bT2[i]           = make_float2(mp1_w1[l * 128 + 64 + k], mp1_w1[(l + 32) * 128 + 64 + k]);
        g_w1bT2[64 * 32 + i] = make_float2(mp2_w1[l * 128 + 64 + k], mp2_w1[(l + 32) * 128 + 64 + k]);
        g_pqT2[i] = make_float2(pq_w[l * 64 + k], pq_w[(l + 32) * 64 + k]);
        float hv = 0.f;
        if (l < 8)       hv = op_w[l * 64 + k];
        else if (l < 18) hv = c1_w[(l - 8) * 64 + k];
        else if (l < 28) hv = c2_w[(l - 18) * 64 + k];
        g_headsT[i] = hv;
    }
    for (int i = tid; i < 72 * 96; i += stride) {
        int k = i / 96, g = (i % 96) / 32, l = i % 32;
        g_wihT2[i] = make_float2(gru_wih[(g * 64 + l) * 72 + k],
                                 gru_wih[(g * 64 + l + 32) * 72 + k]);
    }
    for (int i = tid; i < 64 * 96; i += stride) {
        int k = i / 96, g = (i % 96) / 32, l = i % 32;
        g_whhT2[i] = make_float2(gru_whh[(g * 64 + l) * 64 + k],
                                 gru_whh[(g * 64 + l + 32) * 64 + k]);
    }
}

// packed 2-wide FMA: acc.{x,y} += {ax,ay} * {bx,by}. The mov.b64 register-pair
// plumbing is coalesced by ptxas when halves are register-adjacent (float4 fields).
__device__ __forceinline__ void fma2(float2& acc, float ax, float ay, float bx, float by) {
    asm("{\n\t"
        ".reg .b64 ra, rb, rc;\n\t"
        "mov.b64 ra, {%2, %3};\n\t"
        "mov.b64 rb, {%4, %5};\n\t"
        "mov.b64 rc, {%0, %1};\n\t"
        "fma.rn.f32x2 rc, ra, rb, rc;\n\t"
        "mov.b64 {%0, %1}, rc;\n\t"
        "}"
        : "+f"(acc.x), "+f"(acc.y)
        : "f"(ax), "f"(ay), "f"(bx), "f"(by));
}

__device__ __forceinline__ float wsum(float v) {
#pragma unroll
    for (int o = 16; o > 0; o >>= 1) v += __shfl_xor_sync(0xffffffffu, v, o);
    return v;
}

// W = warps/block, SHN = max nodes held, MAXC = max chunk count, [CMIN,CMAX] cnt range
template <int W, int SHN, int MAXC, int CMIN, int CMAX>
__global__ void __launch_bounds__(W * 32)
mp_kernel(const float* __restrict__ node_feats, const int* __restrict__ n_nodes,
          const float* __restrict__ rnn_state, const float* __restrict__ prev_op,
          const float* __restrict__ ne_w, const float* __restrict__ ne_b,
          const float* __restrict__ mp1_b1, const float* __restrict__ mp1_b2,
          const float* __restrict__ n1_g, const float* __restrict__ n1_b,
          const float* __restrict__ mp2_b1, const float* __restrict__ mp2_b2,
          const float* __restrict__ n2_g, const float* __restrict__ n2_b,
          const float* __restrict__ gru_bih, const float* __restrict__ gru_bhh,
          const float* __restrict__ op_b, const float* __restrict__ c1_b,
          const float* __restrict__ c2_b,
          const float* __restrict__ pq_b,
          const float* __restrict__ pk_w, const float* __restrict__ pk_b,
          float* __restrict__ out, int B)
{
    extern __shared__ float smem[];
    __shared__ int s_range[2];
    constexpr int ACT = SHN * 64 + CH * 64 + 192;

    // ---- early block-exit: sorted order => block's cnt range from first/last slot ----
    if (threadIdx.x == 0) {
        const int s0 = blockIdx.x * W;
        const int s1 = min(s0 + W - 1, B - 1);
        s_range[0] = n_nodes[g_perm[s0]];
        s_range[1] = n_nodes[g_perm[s1]];
    }
    __syncthreads();
    if (s_range[0] > CMAX || s_range[1] < CMIN) return;   // whole block out of class

    // ---- stage all MLP weights once (all threads), single barrier ----
    {
        const float4* src = (const float4*)g_stage;
        float4* dst = (float4*)smem;
        for (int i = threadIdx.x; i < STAGE_FLOATS / 4; i += W * 32) dst[i] = src[i];
    }
    __syncthreads();

    const int warp = threadIdx.x >> 5;
    const int lane = threadIdx.x & 31;
    const int slot = blockIdx.x * W + warp;
    if (slot >= B) return;   // safe: no block-wide barriers after this point
    const long b = g_perm[slot];

    const int o0 = lane, o1 = lane + 32;
    const int cnt = n_nodes[b];
    if (cnt < CMIN || cnt > CMAX) return;   // other kernel variant handles it
    const float inv = 1.0f / (float)cnt;

    float* sh = smem + STAGE_FLOATS + warp * ACT;
    float* su = sh + SHN * 64;
    float* sm = su + CH * 64;
    float* sa = sm + 64;
    float* sb = sa + 64;

    const long OC1 = (long)B * 8;
    const long OC2 = (long)B * 18;
    const long OPTR = (long)B * 28;
    const long OST = (long)B * 48;

    // ---- load node feats (only cnt rows) into su (alias) ----
    {
        const float4* nf = (const float4*)(node_feats + b * (MAXN * 16));
        float4* d4 = (float4*)su;
        const int tot4 = cnt * 4;
        for (int i = lane; i < tot4; i += 32) d4[i] = nf[i];
    }
    const float st0 = rnn_state[b * 64 + o0];
    const float st1 = rnn_state[b * 64 + o1];
    sa[o0] = st0; sa[o1] = st1;
    const float4 pva = *(const float4*)(prev_op + b * 8);
    const float4 pvb = *(const float4*)(prev_op + b * 8 + 4);
    __syncwarp();

    // ---- encoder: h = nf @ ne_w^T + ne_b ; msg = masked mean (f32x2 packed) ----
    float msg0 = 0.f, msg1 = 0.f;
    {
        float4 w0[4], w1[4];
#pragma unroll
        for (int kc = 0; kc < 4; kc++) {
            w0[kc] = *(const float4*)(ne_w + o0 * 16 + kc * 4);
            w1[kc] = *(const float4*)(ne_w + o1 * 16 + kc * 4);
        }
        const float nb0 = ne_b[o0], nb1 = ne_b[o1];
#pragma unroll
        for (int c = 0; c < MAXC; c++) {
            const int base = c * CH;
            if (base < cnt) {
                float2 A0[CH], A1[CH];
#pragma unroll
                for (int i = 0; i < CH; i++) {
                    A0[i] = make_float2(nb0, 0.f);
                    A1[i] = make_float2(nb1, 0.f);
                }
#pragma unroll
                for (int kc = 0; kc < 4; kc++) {
#pragma unroll
                    for (int i = 0; i < CH; i++) {
                        float4 xv = *(const float4*)(su + (base + i) * 16 + kc * 4);
                        fma2(A0[i], xv.x, xv.y, w0[kc].x, w0[kc].y);
                        fma2(A0[i], xv.z, xv.w, w0[kc].z, w0[kc].w);
                        fma2(A1[i], xv.x, xv.y, w1[kc].x, w1[kc].y);
                        fma2(A1[i], xv.z, xv.w, w1[kc].z, w1[kc].w);
                    }
                }
#pragma unroll
                for (int i = 0; i < CH; i++) {
                    const int n = base + i;
                    if (n < cnt) {
                        const float h0 = A0[i].x + A0[i].y;
                        const float h1 = A1[i].x + A1[i].y;
                        msg0 += h0; msg1 += h1;
                        sh[n * 64 + o0] = h0;
                        sh[n * 64 + o1] = h1;
                    }
                }
            }
        }
    }
    msg0 *= inv; msg1 *= inv;
    __syncwarp();
    sm[o0] = msg0; sm[o1] = msg1;
    __syncwarp();

    // ---- two message-passing blocks (weights in smem, f32x2 packed) ----
#pragma unroll 1
    for (int blk = 0; blk < 2; blk++) {
        const float* W1s = smem + blk * 8704;
        const float* W2s = smem + blk * 8704 + 4352;
        const float* b1p = blk ? mp2_b1 : mp1_b1;
        const float* b2p = blk ? mp2_b2 : mp1_b2;
        const float* gp  = blk ? n2_g : n1_g;
        const float* lbp = blk ? n2_b : n1_b;

        // msg-dependent part of layer1 (row-invariant) via transposed global table
        float mm0 = b1p[o0], mm1 = b1p[o1];
        {
            const float2* wb = g_w1bT2 + blk * (64 * 32);
#pragma unroll 4
            for (int k = 0; k < 64; k++) {
                const float xm = sm[k];
                const float2 w = wb[k * 32 + lane];
                mm0 = fmaf(xm, w.x, mm0);
                mm1 = fmaf(xm, w.y, mm1);
            }
        }
        const float* w1r0 = W1s + o0 * 68;
        const float* w1r1 = W1s + o1 * 68;
        const float* w2r0 = W2s + o0 * 68;
        const float* w2r1 = W2s + o1 * 68;
        const float bb20 = b2p[o0], bb21 = b2p[o1];
        const float g0 = gp[o0], g1 = gp[o1];
        const float lb0 = lbp[o0], lb1 = lbp[o1];

        float nm0 = 0.f, nm1 = 0.f;
#pragma unroll
        for (int c = 0; c < MAXC; c++) {
            const int base = c * CH;
            if (base < cnt) {
                // layer1: u = relu(h @ W1a^T + mm)
                float2 A0[CH], A1[CH];
#pragma unroll
                for (int i = 0; i < CH; i++) {
                    A0[i] = make_float2(mm0, 0.f);
                    A1[i] = make_float2(mm1, 0.f);
                }
#pragma unroll
                for (int kc = 0; kc < 16; kc++) {
                    float4 wa = *(const float4*)(w1r0 + kc * 4);
                    float4 wb = *(const float4*)(w1r1 + kc * 4);
#pragma unroll
                    for (int i = 0; i < CH; i++) {
                        float4 xv = *(const float4*)(sh + (base + i) * 64 + kc * 4);
                        fma2(A0[i], xv.x, xv.y, wa.x, wa.y);
                        fma2(A0[i], xv.z, xv.w, wa.z, wa.w);
                        fma2(A1[i], xv.x, xv.y, wb.x, wb.y);
                        fma2(A1[i], xv.z, xv.w, wb.z, wb.w);
                    }
                }
#pragma unroll
                for (int i = 0; i < CH; i++) {
                    su[i * 64 + o0] = fmaxf(A0[i].x + A0[i].y, 0.f);
                    su[i * 64 + o1] = fmaxf(A1[i].x + A1[i].y, 0.f);
                }
                __syncwarp();
                // layer2 + residual + LN + mask
                float2 V0[CH], V1[CH];
#pragma unroll
                for (int i = 0; i < CH; i++) {
                    V0[i] = make_float2(bb20, 0.f);
                    V1[i] = make_float2(bb21, 0.f);
                }
#pragma unroll
                for (int kc = 0; kc < 16; kc++) {
                    float4 wa = *(const float4*)(w2r0 + kc * 4);
                    float4 wb = *(const float4*)(w2r1 + kc * 4);
#pragma unroll
                    for (int i = 0; i < CH; i++) {
                        float4 xv = *(const float4*)(su + i * 64 + kc * 4);
                        fma2(V0[i], xv.x, xv.y, wa.x, wa.y);
                        fma2(V0[i], xv.z, xv.w, wa.z, wa.w);
                        fma2(V1[i], xv.x, xv.y, wb.x, wb.y);
                        fma2(V1[i], xv.z, xv.w, wb.z, wb.w);
                    }
                }
#pragma unroll
                for (int i = 0; i < CH; i++) {
                    const int n = base + i;
                    if (n < cnt) {
                        float x0 = V0[i].x + V0[i].y + sh[n * 64 + o0];
                        float x1v = V1[i].x + V1[i].y + sh[n * 64 + o1];
                        float mu = wsum(x0 + x1v) * (1.0f / 64.0f);
                        float d0 = x0 - mu, d1 = x1v - mu;
                        float var = wsum(d0 * d0 + d1 * d1) * (1.0f / 64.0f);
                        float rs = rsqrtf(var + 1e-5f);
                        float h0 = d0 * rs * g0 + lb0;
                        float h1 = d1 * rs * g1 + lb1;
                        nm0 += h0; nm1 += h1;
                        sh[n * 64 + o0] = h0;
                        sh[n * 64 + o1] = h1;
                    }
                }
                __syncwarp();
            }
        }
        msg0 = nm0 * inv; msg1 = nm1 * inv;
        __syncwarp();
        sm[o0] = msg0; sm[o1] = msg1;
        __syncwarp();
    }

    // ---- GRU cell via transposed, lane-pair-packed weights (coalesced) ----
    float gir0 = gru_bih[o0],       gir1 = gru_bih[o1];
    float giz0 = gru_bih[64 + o0],  giz1 = gru_bih[64 + o1];
    float gin0 = gru_bih[128 + o0], gin1 = gru_bih[128 + o1];
    float ghr0 = gru_bhh[o0],       ghr1 = gru_bhh[o1];
    float ghz0 = gru_bhh[64 + o0],  ghz1 = gru_bhh[64 + o1];
    float ghn0 = gru_bhh[128 + o0], ghn1 = gru_bhh[128 + o1];
#pragma unroll 4
    for (int k = 0; k < 64; k++) {
        const float xm = sm[k];
        const float2* wk = g_wihT2 + k * 96;
        const float2 wr = wk[lane];
        const float2 wz = wk[32 + lane];
        const float2 wn = wk[64 + lane];
        gir0 = fmaf(xm, wr.x, gir0); gir1 = fmaf(xm, wr.y, gir1);
        giz0 = fmaf(xm, wz.x, giz0); giz1 = fmaf(xm, wz.y, giz1);
        gin0 = fmaf(xm, wn.x, gin0); gin1 = fmaf(xm, wn.y, gin1);
        const float xs = sa[k];
        const float2* vk = g_whhT2 + k * 96;
        const float2 vr = vk[lane];
        const float2 vz = vk[32 + lane];
        const float2 vn = vk[64 + lane];
        ghr0 = fmaf(xs, vr.x, ghr0); ghr1 = fmaf(xs, vr.y, ghr1);
        ghz0 = fmaf(xs, vz.x, ghz0); ghz1 = fmaf(xs, vz.y, ghz1);
        ghn0 = fmaf(xs, vn.x, ghn0); ghn1 = fmaf(xs, vn.y, ghn1);
    }
    {
        const float pv[8] = {pva.x, pva.y, pva.z, pva.w, pvb.x, pvb.y, pvb.z, pvb.w};
#pragma unroll
        for (int k = 0; k < 8; k++) {
            const float xp = pv[k];
            const float2* wk = g_wihT2 + (64 + k) * 96;
            const float2 wr = wk[lane];
            const float2 wz = wk[32 + lane];
            const float2 wn = wk[64 + lane];
            gir0 = fmaf(xp, wr.x, gir0); gir1 = fmaf(xp, wr.y, gir1);
            giz0 = fmaf(xp, wz.x, giz0); giz1 = fmaf(xp, wz.y, giz1);
            gin0 = fmaf(xp, wn.x, gin0); gin1 = fmaf(xp, wn.y, gin1);
        }
    }

    const float r0 = 1.0f / (1.0f + expf(-(gir0 + ghr0)));
    const float r1 = 1.0f / (1.0f + expf(-(gir1 + ghr1)));
    const float z0 = 1.0f / (1.0f + expf(-(giz0 + ghz0)));
    const float z1 = 1.0f / (1.0f + expf(-(giz1 + ghz1)));
    const float nn0 = tanhf(gin0 + r0 * ghn0);
    const float nn1 = tanhf(gin1 + r1 * ghn1);
    const float ns0 = (1.0f - z0) * nn0 + z0 * st0;
    const float ns1 = (1.0f - z1) * nn1 + z1 * st1;

    out[OST + b * 64 + o0] = ns0;
    out[OST + b * 64 + o1] = ns1;
    sb[o0] = ns0; sb[o1] = ns1;
    __syncwarp();

    // ---- heads via transposed matrix (coalesced; one output per lane) ----
    {
        float hb = 0.f; long off = -1;
        if (lane < 8)       { hb = op_b[lane];      off = b * 8 + lane; }
        else if (lane < 18) { hb = c1_b[lane - 8];  off = OC1 + b * 10 + (lane - 8); }
        else if (lane < 28) { hb = c2_b[lane - 18]; off = OC2 + b * 10 + (lane - 18); }
        float acc = hb;
#pragma unroll 4
        for (int k = 0; k < 64; k++) acc = fmaf(sb[k], g_headsT[k * 32 + lane], acc);
        if (off >= 0) out[off] = acc;
    }

    // ---- query via transposed pq, then qa = pk_w^T @ q ----
    float q0 = pq_b[o0], q1 = pq_b[o1];
#pragma unroll 4
    for (int k = 0; k < 64; k++) {
        const float xv = sb[k];
        const float2 w = g_pqT2[k * 32 + lane];
        q0 = fmaf(xv, w.x, q0); q1 = fmaf(xv, w.y, q1);
    }
    __syncwarp();
    sa[o0] = q0; sa[o1] = q1;
    __syncwarp();

    float qa0 = 0.f, qa1 = 0.f;
#pragma unroll 8
    for (int o = 0; o < 64; o++) {
        const float qv = sa[o];
        qa0 = fmaf(qv, pk_w[o * 64 + o0], qa0);
        qa1 = fmaf(qv, pk_w[o * 64 + o1], qa1);
    }
    const float qb = wsum(q0 * pk_b[o0] + q1 * pk_b[o1]);

    // ---- pointer logits ----
    for (int n = 0; n < cnt; n++) {
        float p = sh[n * 64 + o0] * qa0 + sh[n * 64 + o1] * qa1;
        float val = wsum(p) + qb;
        if (lane == 0) out[OPTR + b * 20 + n] = val;
    }
    for (int n = cnt + lane; n < MAXN; n += 32) out[OPTR + b * 20 + n] = -1e9f;
}

#define ACT_OF(SHN) ((SHN) * 64 + CH * 64 + 192)

extern "C" void kernel_launch(void* const* d_in, const int* in_sizes, int n_in,
                              void* d_out, int out_size) {
    const int B = in_sizes[1];  // n_nodes element count
    const int* n_nodes = (const int*)d_in[1];

    // cnt-sort elements so warps within a block get similar node counts
    sort_zero<<<1, 32>>>();
    sort_count<<<128, 256>>>(n_nodes, B);
    sort_scan<<<1, 32>>>();
    sort_scatter<<<(B + 255) / 256, 256>>>(n_nodes, B);

    prep_kernel<<<64, 256>>>(
        (const float*)d_in[6],  (const float*)d_in[8],   // mp1_w1, mp1_w2
        (const float*)d_in[12], (const float*)d_in[14],  // mp2_w1, mp2_w2
        (const float*)d_in[18], (const float*)d_in[19],  // gru_wih, gru_whh
        (const float*)d_in[28],                          // pq_w
        (const float*)d_in[22], (const float*)d_in[24], (const float*)d_in[26]); // op_w,c1_w,c2_w

    auto kern_small = mp_kernel<W_SMALL, 10, 2, 1, 10>;
    auto kern_big   = mp_kernel<W_BIG,   20, 4, 11, 20>;

    const size_t smem_small = (size_t)(STAGE_FLOATS + W_SMALL * ACT_OF(10)) * sizeof(float);
    const size_t smem_big   = (size_t)(STAGE_FLOATS + W_BIG   * ACT_OF(20)) * sizeof(float);
    cudaFuncSetAttribute(kern_small, cudaFuncAttributeMaxDynamicSharedMemorySize, (int)smem_small);
    cudaFuncSetAttribute(kern_big,   cudaFuncAttributeMaxDynamicSharedMemorySize, (int)smem_big);

#define MP_ARGS \
        (const float*)d_in[0], (const int*)d_in[1], \
        (const float*)d_in[2], (const float*)d_in[3], \
        (const float*)d_in[4], (const float*)d_in[5], \
        (const float*)d_in[7], (const float*)d_in[9], \
        (const float*)d_in[10], (const float*)d_in[11], \
        (const float*)d_in[13], (const float*)d_in[15], \
        (const float*)d_in[16], (const float*)d_in[17], \
        (const float*)d_in[20], (const float*)d_in[21], \
        (const float*)d_in[23], (const float*)d_in[25], (const float*)d_in[27], \
        (const float*)d_in[29], \
        (const float*)d_in[30], (const float*)d_in[31], \
        (float*)d_out, B

    kern_small<<<(B + W_SMALL - 1) / W_SMALL, W_SMALL * 32, smem_small>>>(MP_ARGS);
    kern_big  <<<(B + W_BIG   - 1) / W_BIG,   W_BIG   * 32, smem_big  >>>(MP_ARGS);
#undef MP_ARGS
}